// round 5
// baseline (speedup 1.0000x reference)
#include <cuda_runtime.h>
#include <math.h>

// Shapes (fixed for this problem)
//  B=8, L=1024, D=1024, H=8, DH=128, BH=64, VOCAB=32000
//  SCALE = (DH//H)^-0.5 = 0.25
//  Output: [8, 2048] f32 layernorm of [maxpool | meanpool]

#define N_B    8
#define N_L    1024
#define N_D    1024
#define N_BH   64
#define N_DH   128
#define SCALE_F 0.25f
#define EPS_F   1e-5f

// ---------------------------------------------------------------------------
// Scratch (static __device__ arrays; no allocation allowed)
// ---------------------------------------------------------------------------
__device__ float g_x[8u * 1024u * 1024u];   // embedded input  [B,L,D]
__device__ float g_q[8u * 1024u * 1024u];   // Q, later reused as r = x + out
__device__ float g_k[8u * 1024u * 1024u];   // K
__device__ float g_v[8u * 1024u * 1024u];   // V
__device__ float g_c[8u * 1024u * 1024u];   // ctx
__device__ float g_s[67108864u];            // scores/probs [64,1024,1024] (256MB)
__device__ float g_nb[8 * 1024];            // -inf mask bias per (batch,key)
__device__ float g_agg[8 * 2048];           // pooled features

// ---------------------------------------------------------------------------
// Block reductions
// ---------------------------------------------------------------------------
__device__ __forceinline__ float blockSum(float v) {
    __shared__ float sh[32];
    int lane = threadIdx.x & 31, wid = threadIdx.x >> 5;
    #pragma unroll
    for (int o = 16; o > 0; o >>= 1) v += __shfl_xor_sync(0xffffffffu, v, o);
    if (lane == 0) sh[wid] = v;
    __syncthreads();
    int nw = blockDim.x >> 5;
    float r = (threadIdx.x < (unsigned)nw) ? sh[threadIdx.x] : 0.0f;
    if (wid == 0) {
        #pragma unroll
        for (int o = 16; o > 0; o >>= 1) r += __shfl_xor_sync(0xffffffffu, r, o);
        if (lane == 0) sh[0] = r;
    }
    __syncthreads();
    float out = sh[0];
    __syncthreads();
    return out;
}

__device__ __forceinline__ float blockMax(float v) {
    __shared__ float sh[32];
    int lane = threadIdx.x & 31, wid = threadIdx.x >> 5;
    #pragma unroll
    for (int o = 16; o > 0; o >>= 1) v = fmaxf(v, __shfl_xor_sync(0xffffffffu, v, o));
    if (lane == 0) sh[wid] = v;
    __syncthreads();
    int nw = blockDim.x >> 5;
    float r = (threadIdx.x < (unsigned)nw) ? sh[threadIdx.x] : -INFINITY;
    if (wid == 0) {
        #pragma unroll
        for (int o = 16; o > 0; o >>= 1) r = fmaxf(r, __shfl_xor_sync(0xffffffffu, r, o));
        if (lane == 0) sh[0] = r;
    }
    __syncthreads();
    float out = sh[0];
    __syncthreads();
    return out;
}

// ---------------------------------------------------------------------------
// Embedding gather: x[row,:] = emb[tok[row],:]   (8192 rows x 1024 f32)
// ---------------------------------------------------------------------------
__global__ void embed_kernel(const int* __restrict__ tokens,
                             const float* __restrict__ emb,
                             float* __restrict__ x) {
    int row = blockIdx.x;
    int tok = tokens[row];
    const float4* src = (const float4*)(emb + (long)tok * N_D);
    float4* dst = (float4*)(x + (long)row * N_D);
    dst[threadIdx.x] = src[threadIdx.x];      // 256 threads * float4 = 1024
}

// mask bias: nb[b,k] = (tokens[b,k]==0) ? -inf : 0
__global__ void mask_kernel(const int* __restrict__ tokens, float* __restrict__ nb) {
    int i = blockIdx.x * blockDim.x + threadIdx.x;
    nb[i] = (tokens[i] == 0) ? -INFINITY : 0.0f;
}

// ---------------------------------------------------------------------------
// Generic fp32 GEMM, 128x128x8 tile, 256 threads, 8x8 microtile.
//   C[M,N] = A[M,K] * op(B) (+bias) (+res)
//   TB=false: B is [K,N] (NN).  TB=true: B is [N,K] (NT, i.e. C=A*B^T).
//   Batched via blockIdx.z strides. All dims multiples of 128 (K mult of 8).
// ---------------------------------------------------------------------------
template <bool TB, bool BIAS, bool RES>
__global__ void __launch_bounds__(256)
gemm128(const float* __restrict__ A, const float* __restrict__ B,
        const float* __restrict__ bias, const float* __restrict__ res,
        float* __restrict__ C, int M, int N, int K,
        long sA, long sB, long sC) {
    __shared__ float As[8][128];
    __shared__ float Bs[8][128];

    int tid = threadIdx.x;
    A += (long)blockIdx.z * sA;
    B += (long)blockIdx.z * sB;
    C += (long)blockIdx.z * sC;
    int row0 = blockIdx.y * 128;
    int col0 = blockIdx.x * 128;

    int a_r  = tid >> 1;
    int a_k4 = (tid & 1) * 4;
    int b_k, b_c;
    if (!TB) { b_k = tid >> 5; b_c = (tid & 31) * 4; }
    else     { b_c = tid >> 1; b_k = (tid & 1) * 4; }

    int tx = tid & 15, ty = tid >> 4;

    float acc[8][8];
    #pragma unroll
    for (int i = 0; i < 8; i++)
        #pragma unroll
        for (int j = 0; j < 8; j++) acc[i][j] = 0.0f;

    for (int k0 = 0; k0 < K; k0 += 8) {
        float4 av = *(const float4*)(A + (long)(row0 + a_r) * K + k0 + a_k4);
        As[a_k4 + 0][a_r] = av.x;
        As[a_k4 + 1][a_r] = av.y;
        As[a_k4 + 2][a_r] = av.z;
        As[a_k4 + 3][a_r] = av.w;
        if (!TB) {
            float4 bv = *(const float4*)(B + (long)(k0 + b_k) * N + col0 + b_c);
            *(float4*)&Bs[b_k][b_c] = bv;
        } else {
            float4 bv = *(const float4*)(B + (long)(col0 + b_c) * K + k0 + b_k);
            Bs[b_k + 0][b_c] = bv.x;
            Bs[b_k + 1][b_c] = bv.y;
            Bs[b_k + 2][b_c] = bv.z;
            Bs[b_k + 3][b_c] = bv.w;
        }
        __syncthreads();
        #pragma unroll
        for (int kk = 0; kk < 8; kk++) {
            float a[8], b[8];
            *(float4*)(a + 0) = *(const float4*)&As[kk][ty * 8 + 0];
            *(float4*)(a + 4) = *(const float4*)&As[kk][ty * 8 + 4];
            *(float4*)(b + 0) = *(const float4*)&Bs[kk][tx * 8 + 0];
            *(float4*)(b + 4) = *(const float4*)&Bs[kk][tx * 8 + 4];
            #pragma unroll
            for (int i = 0; i < 8; i++)
                #pragma unroll
                for (int j = 0; j < 8; j++) acc[i][j] += a[i] * b[j];
        }
        __syncthreads();
    }

    #pragma unroll
    for (int i = 0; i < 8; i++) {
        int r = row0 + ty * 8 + i;
        #pragma unroll
        for (int j = 0; j < 8; j += 4) {
            int c = col0 + tx * 8 + j;
            float4 v = make_float4(acc[i][j], acc[i][j + 1], acc[i][j + 2], acc[i][j + 3]);
            if (BIAS) {
                float4 bb = *(const float4*)(bias + c);
                v.x += bb.x; v.y += bb.y; v.z += bb.z; v.w += bb.w;
            }
            if (RES) {
                float4 rr = *(const float4*)(res + (long)r * N + c);
                v.x += rr.x; v.y += rr.y; v.z += rr.z; v.w += rr.w;
            }
            *(float4*)(C + (long)r * N + c) = v;
        }
    }
}

// ---------------------------------------------------------------------------
// Softmax over score rows, applying SCALE and the (faithful) bh%8 key mask.
//   S[bh, q, :1024] -> softmax in-place.  grid (1024 q, 64 bh), 256 threads
// ---------------------------------------------------------------------------
__global__ void __launch_bounds__(256)
softmax_kernel(float* __restrict__ S, const float* __restrict__ nb) {
    int bh = blockIdx.y, q = blockIdx.x, tid = threadIdx.x;
    float* row = S + ((long)bh << 20) + ((long)q << 10);
    const float* nbr = nb + ((bh & 7) << 10);

    float vals[4];
    float mx = -INFINITY;
    #pragma unroll
    for (int i = 0; i < 4; i++) {
        int k = tid + i * 256;
        float v = row[k] * SCALE_F + nbr[k];
        vals[i] = v;
        mx = fmaxf(mx, v);
    }
    mx = blockMax(mx);
    float sum = 0.0f;
    #pragma unroll
    for (int i = 0; i < 4; i++) {
        vals[i] = expf(vals[i] - mx);   // exp(-inf)=0 for masked keys
        sum += vals[i];
    }
    sum = blockSum(sum);
    float inv = 1.0f / sum;
    #pragma unroll
    for (int i = 0; i < 4; i++) row[tid + i * 256] = vals[i] * inv;
}

// ---------------------------------------------------------------------------
// Pooling: agg[b, d] = max_l r[b,l,d]; agg[b, D+d] = mean_l r[b,l,d]
//   grid (8 b, 8 dchunk), 128 threads
// ---------------------------------------------------------------------------
__global__ void pool_kernel(const float* __restrict__ r, float* __restrict__ agg) {
    int b = blockIdx.x;
    int d = blockIdx.y * 128 + threadIdx.x;
    const float* base = r + ((long)b << 20) + d;
    float mx = -INFINITY, sm = 0.0f;
    #pragma unroll 4
    for (int l = 0; l < N_L; l++) {
        float v = base[(long)l << 10];
        mx = fmaxf(mx, v);
        sm += v;
    }
    agg[b * 2048 + d]        = mx;
    agg[b * 2048 + 1024 + d] = sm * (1.0f / 1024.0f);
}

// ---------------------------------------------------------------------------
// LayerNorm over 2048 dims (population variance), one block per batch row
// ---------------------------------------------------------------------------
__global__ void __launch_bounds__(256)
ln_kernel(const float* __restrict__ agg, const float* __restrict__ gamma,
          const float* __restrict__ beta, float* __restrict__ out) {
    int b = blockIdx.x, tid = threadIdx.x;
    const float* a = agg + b * 2048;
    float s = 0.0f;
    #pragma unroll
    for (int i = 0; i < 8; i++) s += a[tid + i * 256];
    s = blockSum(s);
    float mu = s * (1.0f / 2048.0f);
    float vs = 0.0f;
    #pragma unroll
    for (int i = 0; i < 8; i++) {
        float d = a[tid + i * 256] - mu;
        vs += d * d;
    }
    vs = blockSum(vs);
    float inv = rsqrtf(vs * (1.0f / 2048.0f) + EPS_F);
    #pragma unroll
    for (int i = 0; i < 8; i++) {
        int k = tid + i * 256;
        out[b * 2048 + k] = (a[k] - mu) * inv * gamma[k] + beta[k];
    }
}

// ---------------------------------------------------------------------------
// Launch
// ---------------------------------------------------------------------------
extern "C" void kernel_launch(void* const* d_in, const int* in_sizes, int n_in,
                              void* d_out, int out_size) {
    const int*   tokens = (const int*)  d_in[0];
    const float* emb    = (const float*)d_in[1];
    const float* Wq     = (const float*)d_in[2];
    const float* bq     = (const float*)d_in[3];
    const float* Wk     = (const float*)d_in[4];
    const float* bk     = (const float*)d_in[5];
    const float* Wv     = (const float*)d_in[6];
    const float* bv     = (const float*)d_in[7];
    const float* Wo     = (const float*)d_in[8];
    const float* bo     = (const float*)d_in[9];
    const float* gamma  = (const float*)d_in[10];
    const float* beta   = (const float*)d_in[11];
    float* out = (float*)d_out;

    float *x, *q, *k, *v, *c, *s, *nb, *agg;
    cudaGetSymbolAddress((void**)&x,   g_x);
    cudaGetSymbolAddress((void**)&q,   g_q);
    cudaGetSymbolAddress((void**)&k,   g_k);
    cudaGetSymbolAddress((void**)&v,   g_v);
    cudaGetSymbolAddress((void**)&c,   g_c);
    cudaGetSymbolAddress((void**)&s,   g_s);
    cudaGetSymbolAddress((void**)&nb,  g_nb);
    cudaGetSymbolAddress((void**)&agg, g_agg);

    // 1. embed + mask
    embed_kernel<<<N_B * N_L, 256>>>(tokens, emb, x);
    mask_kernel<<<8, 1024>>>(tokens, nb);

    // 2. Q/K/V projections: [8192,1024] x [1024,1024] + bias
    dim3 gProj(8, 64, 1);
    gemm128<false, true, false><<<gProj, 256>>>(x, Wq, bq, nullptr, q, 8192, 1024, 1024, 0, 0, 0);
    gemm128<false, true, false><<<gProj, 256>>>(x, Wk, bk, nullptr, k, 8192, 1024, 1024, 0, 0, 0);
    gemm128<false, true, false><<<gProj, 256>>>(x, Wv, bv, nullptr, v, 8192, 1024, 1024, 0, 0, 0);

    // 3. scores = Q K^T (batched over 64 flat heads); scale+mask applied in softmax
    dim3 gS(8, 8, 64);
    gemm128<true, false, false><<<gS, 256>>>(q, k, nullptr, nullptr, s,
                                             1024, 1024, 128,
                                             131072L, 131072L, 1048576L);

    // 4. softmax rows (scale 0.25, mask batch = bh % 8, faithful to reference)
    softmax_kernel<<<dim3(1024, 64), 256>>>(s, nb);

    // 5. ctx = P V
    dim3 gPV(1, 8, 64);
    gemm128<false, false, false><<<gPV, 256>>>(s, v, nullptr, nullptr, c,
                                               1024, 128, 1024,
                                               1048576L, 131072L, 131072L);

    // 6. r = x + ctx @ Wo + bo   (store into g_q, which is free now)
    gemm128<false, true, true><<<gProj, 256>>>(c, Wo, bo, x, q, 8192, 1024, 1024, 0, 0, 0);

    // 7. max/mean pool over L
    pool_kernel<<<dim3(8, 8), 128>>>(q, agg);

    // 8. layernorm -> output [8, 2048]
    ln_kernel<<<8, 256>>>(agg, gamma, beta, out);
}

// round 6
// speedup vs baseline: 1.0005x; 1.0005x over previous
#include <cuda_runtime.h>
#include <math.h>

// Shapes (fixed for this problem)
//  B=8, L=1024, D=1024, H=8, DH=128, BH=64, VOCAB=32000
//  SCALE = (DH//H)^-0.5 = 0.25
//  Output: [8, 2048] f32 layernorm of [maxpool | meanpool]

#define N_B    8
#define N_L    1024
#define N_D    1024
#define N_BH   64
#define N_DH   128
#define SCALE_F 0.25f
#define EPS_F   1e-5f

// ---------------------------------------------------------------------------
// Scratch (static __device__ arrays; no allocation allowed)
// ---------------------------------------------------------------------------
__device__ float g_x[8u * 1024u * 1024u];   // embedded input  [B,L,D]
__device__ float g_q[8u * 1024u * 1024u];   // Q, later reused as r = x + out
__device__ float g_k[8u * 1024u * 1024u];   // K
__device__ float g_v[8u * 1024u * 1024u];   // V
__device__ float g_c[8u * 1024u * 1024u];   // ctx
__device__ float g_s[67108864u];            // scores/probs [64,1024,1024] (256MB)
__device__ float g_nb[8 * 1024];            // -inf mask bias per (batch,key)
__device__ float g_agg[8 * 2048];           // pooled features

// ---------------------------------------------------------------------------
// Block reductions
// ---------------------------------------------------------------------------
__device__ __forceinline__ float blockSum(float v) {
    __shared__ float sh[32];
    int lane = threadIdx.x & 31, wid = threadIdx.x >> 5;
    #pragma unroll
    for (int o = 16; o > 0; o >>= 1) v += __shfl_xor_sync(0xffffffffu, v, o);
    if (lane == 0) sh[wid] = v;
    __syncthreads();
    int nw = blockDim.x >> 5;
    float r = (threadIdx.x < (unsigned)nw) ? sh[threadIdx.x] : 0.0f;
    if (wid == 0) {
        #pragma unroll
        for (int o = 16; o > 0; o >>= 1) r += __shfl_xor_sync(0xffffffffu, r, o);
        if (lane == 0) sh[0] = r;
    }
    __syncthreads();
    float out = sh[0];
    __syncthreads();
    return out;
}

__device__ __forceinline__ float blockMax(float v) {
    __shared__ float sh[32];
    int lane = threadIdx.x & 31, wid = threadIdx.x >> 5;
    #pragma unroll
    for (int o = 16; o > 0; o >>= 1) v = fmaxf(v, __shfl_xor_sync(0xffffffffu, v, o));
    if (lane == 0) sh[wid] = v;
    __syncthreads();
    int nw = blockDim.x >> 5;
    float r = (threadIdx.x < (unsigned)nw) ? sh[threadIdx.x] : -INFINITY;
    if (wid == 0) {
        #pragma unroll
        for (int o = 16; o > 0; o >>= 1) r = fmaxf(r, __shfl_xor_sync(0xffffffffu, r, o));
        if (lane == 0) sh[0] = r;
    }
    __syncthreads();
    float out = sh[0];
    __syncthreads();
    return out;
}

// ---------------------------------------------------------------------------
// Embedding gather: x[row,:] = emb[tok[row],:]   (8192 rows x 1024 f32)
// ---------------------------------------------------------------------------
__global__ void embed_kernel(const int* __restrict__ tokens,
                             const float* __restrict__ emb,
                             float* __restrict__ x) {
    int row = blockIdx.x;
    int tok = tokens[row];
    const float4* src = (const float4*)(emb + (long)tok * N_D);
    float4* dst = (float4*)(x + (long)row * N_D);
    dst[threadIdx.x] = src[threadIdx.x];      // 256 threads * float4 = 1024
}

// mask bias: nb[b,k] = (tokens[b,k]==0) ? -inf : 0
__global__ void mask_kernel(const int* __restrict__ tokens, float* __restrict__ nb) {
    int i = blockIdx.x * blockDim.x + threadIdx.x;
    nb[i] = (tokens[i] == 0) ? -INFINITY : 0.0f;
}

// ---------------------------------------------------------------------------
// Generic fp32 GEMM, 128x128x8 tile, 256 threads, 8x8 microtile.
//   C[M,N] = A[M,K] * op(B) (+bias) (+res)
//   TB=false: B is [K,N] (NN).  TB=true: B is [N,K] (NT, i.e. C=A*B^T).
//   Batched via blockIdx.z strides. All dims multiples of 128 (K mult of 8).
// ---------------------------------------------------------------------------
template <bool TB, bool BIAS, bool RES>
__global__ void __launch_bounds__(256)
gemm128(const float* __restrict__ A, const float* __restrict__ B,
        const float* __restrict__ bias, const float* __restrict__ res,
        float* __restrict__ C, int M, int N, int K,
        long sA, long sB, long sC) {
    __shared__ float As[8][128];
    __shared__ float Bs[8][128];

    int tid = threadIdx.x;
    A += (long)blockIdx.z * sA;
    B += (long)blockIdx.z * sB;
    C += (long)blockIdx.z * sC;
    int row0 = blockIdx.y * 128;
    int col0 = blockIdx.x * 128;

    int a_r  = tid >> 1;
    int a_k4 = (tid & 1) * 4;
    int b_k, b_c;
    if (!TB) { b_k = tid >> 5; b_c = (tid & 31) * 4; }
    else     { b_c = tid >> 1; b_k = (tid & 1) * 4; }

    int tx = tid & 15, ty = tid >> 4;

    float acc[8][8];
    #pragma unroll
    for (int i = 0; i < 8; i++)
        #pragma unroll
        for (int j = 0; j < 8; j++) acc[i][j] = 0.0f;

    for (int k0 = 0; k0 < K; k0 += 8) {
        float4 av = *(const float4*)(A + (long)(row0 + a_r) * K + k0 + a_k4);
        As[a_k4 + 0][a_r] = av.x;
        As[a_k4 + 1][a_r] = av.y;
        As[a_k4 + 2][a_r] = av.z;
        As[a_k4 + 3][a_r] = av.w;
        if (!TB) {
            float4 bv = *(const float4*)(B + (long)(k0 + b_k) * N + col0 + b_c);
            *(float4*)&Bs[b_k][b_c] = bv;
        } else {
            float4 bv = *(const float4*)(B + (long)(col0 + b_c) * K + k0 + b_k);
            Bs[b_k + 0][b_c] = bv.x;
            Bs[b_k + 1][b_c] = bv.y;
            Bs[b_k + 2][b_c] = bv.z;
            Bs[b_k + 3][b_c] = bv.w;
        }
        __syncthreads();
        #pragma unroll
        for (int kk = 0; kk < 8; kk++) {
            float a[8], b[8];
            *(float4*)(a + 0) = *(const float4*)&As[kk][ty * 8 + 0];
            *(float4*)(a + 4) = *(const float4*)&As[kk][ty * 8 + 4];
            *(float4*)(b + 0) = *(const float4*)&Bs[kk][tx * 8 + 0];
            *(float4*)(b + 4) = *(const float4*)&Bs[kk][tx * 8 + 4];
            #pragma unroll
            for (int i = 0; i < 8; i++)
                #pragma unroll
                for (int j = 0; j < 8; j++) acc[i][j] += a[i] * b[j];
        }
        __syncthreads();
    }

    #pragma unroll
    for (int i = 0; i < 8; i++) {
        int r = row0 + ty * 8 + i;
        #pragma unroll
        for (int j = 0; j < 8; j += 4) {
            int c = col0 + tx * 8 + j;
            float4 v = make_float4(acc[i][j], acc[i][j + 1], acc[i][j + 2], acc[i][j + 3]);
            if (BIAS) {
                float4 bb = *(const float4*)(bias + c);
                v.x += bb.x; v.y += bb.y; v.z += bb.z; v.w += bb.w;
            }
            if (RES) {
                float4 rr = *(const float4*)(res + (long)r * N + c);
                v.x += rr.x; v.y += rr.y; v.z += rr.z; v.w += rr.w;
            }
            *(float4*)(C + (long)r * N + c) = v;
        }
    }
}

// ---------------------------------------------------------------------------
// Softmax over score rows, applying SCALE and the (faithful) bh%8 key mask.
//   S[bh, q, :1024] -> softmax in-place.  grid (1024 q, 64 bh), 256 threads
// ---------------------------------------------------------------------------
__global__ void __launch_bounds__(256)
softmax_kernel(float* __restrict__ S, const float* __restrict__ nb) {
    int bh = blockIdx.y, q = blockIdx.x, tid = threadIdx.x;
    float* row = S + ((long)bh << 20) + ((long)q << 10);
    const float* nbr = nb + ((bh & 7) << 10);

    float vals[4];
    float mx = -INFINITY;
    #pragma unroll
    for (int i = 0; i < 4; i++) {
        int k = tid + i * 256;
        float v = row[k] * SCALE_F + nbr[k];
        vals[i] = v;
        mx = fmaxf(mx, v);
    }
    mx = blockMax(mx);
    float sum = 0.0f;
    #pragma unroll
    for (int i = 0; i < 4; i++) {
        vals[i] = expf(vals[i] - mx);   // exp(-inf)=0 for masked keys
        sum += vals[i];
    }
    sum = blockSum(sum);
    float inv = 1.0f / sum;
    #pragma unroll
    for (int i = 0; i < 4; i++) row[tid + i * 256] = vals[i] * inv;
}

// ---------------------------------------------------------------------------
// Pooling: agg[b, d] = max_l r[b,l,d]; agg[b, D+d] = mean_l r[b,l,d]
//   grid (8 b, 8 dchunk), 128 threads
// ---------------------------------------------------------------------------
__global__ void pool_kernel(const float* __restrict__ r, float* __restrict__ agg) {
    int b = blockIdx.x;
    int d = blockIdx.y * 128 + threadIdx.x;
    const float* base = r + ((long)b << 20) + d;
    float mx = -INFINITY, sm = 0.0f;
    #pragma unroll 4
    for (int l = 0; l < N_L; l++) {
        float v = base[(long)l << 10];
        mx = fmaxf(mx, v);
        sm += v;
    }
    agg[b * 2048 + d]        = mx;
    agg[b * 2048 + 1024 + d] = sm * (1.0f / 1024.0f);
}

// ---------------------------------------------------------------------------
// LayerNorm over 2048 dims (population variance), one block per batch row
// ---------------------------------------------------------------------------
__global__ void __launch_bounds__(256)
ln_kernel(const float* __restrict__ agg, const float* __restrict__ gamma,
          const float* __restrict__ beta, float* __restrict__ out) {
    int b = blockIdx.x, tid = threadIdx.x;
    const float* a = agg + b * 2048;
    float s = 0.0f;
    #pragma unroll
    for (int i = 0; i < 8; i++) s += a[tid + i * 256];
    s = blockSum(s);
    float mu = s * (1.0f / 2048.0f);
    float vs = 0.0f;
    #pragma unroll
    for (int i = 0; i < 8; i++) {
        float d = a[tid + i * 256] - mu;
        vs += d * d;
    }
    vs = blockSum(vs);
    float inv = rsqrtf(vs * (1.0f / 2048.0f) + EPS_F);
    #pragma unroll
    for (int i = 0; i < 8; i++) {
        int k = tid + i * 256;
        out[b * 2048 + k] = (a[k] - mu) * inv * gamma[k] + beta[k];
    }
}

// ---------------------------------------------------------------------------
// Launch
// ---------------------------------------------------------------------------
extern "C" void kernel_launch(void* const* d_in, const int* in_sizes, int n_in,
                              void* d_out, int out_size) {
    const int*   tokens = (const int*)  d_in[0];
    const float* emb    = (const float*)d_in[1];
    const float* Wq     = (const float*)d_in[2];
    const float* bq     = (const float*)d_in[3];
    const float* Wk     = (const float*)d_in[4];
    const float* bk     = (const float*)d_in[5];
    const float* Wv     = (const float*)d_in[6];
    const float* bv     = (const float*)d_in[7];
    const float* Wo     = (const float*)d_in[8];
    const float* bo     = (const float*)d_in[9];
    const float* gamma  = (const float*)d_in[10];
    const float* beta   = (const float*)d_in[11];
    float* out = (float*)d_out;

    float *x, *q, *k, *v, *c, *s, *nb, *agg;
    cudaGetSymbolAddress((void**)&x,   g_x);
    cudaGetSymbolAddress((void**)&q,   g_q);
    cudaGetSymbolAddress((void**)&k,   g_k);
    cudaGetSymbolAddress((void**)&v,   g_v);
    cudaGetSymbolAddress((void**)&c,   g_c);
    cudaGetSymbolAddress((void**)&s,   g_s);
    cudaGetSymbolAddress((void**)&nb,  g_nb);
    cudaGetSymbolAddress((void**)&agg, g_agg);

    // 1. embed + mask
    embed_kernel<<<N_B * N_L, 256>>>(tokens, emb, x);
    mask_kernel<<<8, 1024>>>(tokens, nb);

    // 2. Q/K/V projections: [8192,1024] x [1024,1024] + bias
    dim3 gProj(8, 64, 1);
    gemm128<false, true, false><<<gProj, 256>>>(x, Wq, bq, nullptr, q, 8192, 1024, 1024, 0, 0, 0);
    gemm128<false, true, false><<<gProj, 256>>>(x, Wk, bk, nullptr, k, 8192, 1024, 1024, 0, 0, 0);
    gemm128<false, true, false><<<gProj, 256>>>(x, Wv, bv, nullptr, v, 8192, 1024, 1024, 0, 0, 0);

    // 3. scores = Q K^T (batched over 64 flat heads); scale+mask applied in softmax
    dim3 gS(8, 8, 64);
    gemm128<true, false, false><<<gS, 256>>>(q, k, nullptr, nullptr, s,
                                             1024, 1024, 128,
                                             131072L, 131072L, 1048576L);

    // 4. softmax rows (scale 0.25, mask batch = bh % 8, faithful to reference)
    softmax_kernel<<<dim3(1024, 64), 256>>>(s, nb);

    // 5. ctx = P V
    dim3 gPV(1, 8, 64);
    gemm128<false, false, false><<<gPV, 256>>>(s, v, nullptr, nullptr, c,
                                               1024, 128, 1024,
                                               1048576L, 131072L, 131072L);

    // 6. r = x + ctx @ Wo + bo   (store into g_q, which is free now)
    gemm128<false, true, true><<<gProj, 256>>>(c, Wo, bo, x, q, 8192, 1024, 1024, 0, 0, 0);

    // 7. max/mean pool over L
    pool_kernel<<<dim3(8, 8), 128>>>(q, agg);

    // 8. layernorm -> output [8, 2048]
    ln_kernel<<<8, 256>>>(agg, gamma, beta, out);
}

// round 7
// speedup vs baseline: 2.0391x; 2.0380x over previous
#include <cuda_runtime.h>
#include <math.h>

// Shapes (fixed): B=8, L=1024, D=1024, H=8, DH=128, BH=64
#define N_B    8
#define N_L    1024
#define N_D    1024
#define SCALE_F 0.25f
#define EPS_F   1e-5f

// ---------------------------------------------------------------------------
// Scratch
// ---------------------------------------------------------------------------
__device__ float g_x[8u * 1024u * 1024u];   // embedded input  [B,L,D]
__device__ float g_q[8u * 1024u * 1024u];   // Q, later reused as r = x + out
__device__ float g_k[8u * 1024u * 1024u];   // K
__device__ float g_v[8u * 1024u * 1024u];   // V
__device__ float g_c[8u * 1024u * 1024u];   // ctx
__device__ float g_s[67108864u];            // scores/probs [64,1024,1024]
__device__ float g_nb[8 * 1024];            // -inf mask bias per (batch,key)
__device__ float g_agg[8 * 2048];           // pooled features

// ---------------------------------------------------------------------------
// Helpers
// ---------------------------------------------------------------------------
__device__ __forceinline__ float tf32r(float x) {
    unsigned u;
    asm("cvt.rna.tf32.f32 %0, %1;" : "=r"(u) : "f"(x));
    return __uint_as_float(u);
}

__device__ __forceinline__ float blockSum(float v) {
    __shared__ float sh[32];
    int lane = threadIdx.x & 31, wid = threadIdx.x >> 5;
    #pragma unroll
    for (int o = 16; o > 0; o >>= 1) v += __shfl_xor_sync(0xffffffffu, v, o);
    if (lane == 0) sh[wid] = v;
    __syncthreads();
    int nw = blockDim.x >> 5;
    float r = (threadIdx.x < (unsigned)nw) ? sh[threadIdx.x] : 0.0f;
    if (wid == 0) {
        #pragma unroll
        for (int o = 16; o > 0; o >>= 1) r += __shfl_xor_sync(0xffffffffu, r, o);
        if (lane == 0) sh[0] = r;
    }
    __syncthreads();
    float out = sh[0];
    __syncthreads();
    return out;
}

__device__ __forceinline__ float blockMax(float v) {
    __shared__ float sh[32];
    int lane = threadIdx.x & 31, wid = threadIdx.x >> 5;
    #pragma unroll
    for (int o = 16; o > 0; o >>= 1) v = fmaxf(v, __shfl_xor_sync(0xffffffffu, v, o));
    if (lane == 0) sh[wid] = v;
    __syncthreads();
    int nw = blockDim.x >> 5;
    float r = (threadIdx.x < (unsigned)nw) ? sh[threadIdx.x] : -INFINITY;
    if (wid == 0) {
        #pragma unroll
        for (int o = 16; o > 0; o >>= 1) r = fmaxf(r, __shfl_xor_sync(0xffffffffu, r, o));
        if (lane == 0) sh[0] = r;
    }
    __syncthreads();
    float out = sh[0];
    __syncthreads();
    return out;
}

// ---------------------------------------------------------------------------
// Embedding gather + mask
// ---------------------------------------------------------------------------
__global__ void embed_kernel(const int* __restrict__ tokens,
                             const float* __restrict__ emb,
                             float* __restrict__ x) {
    int row = blockIdx.x;
    int tok = tokens[row];
    const float4* src = (const float4*)(emb + (long)tok * N_D);
    float4* dst = (float4*)(x + (long)row * N_D);
    dst[threadIdx.x] = src[threadIdx.x];
}

__global__ void mask_kernel(const int* __restrict__ tokens, float* __restrict__ nb) {
    int i = blockIdx.x * blockDim.x + threadIdx.x;
    nb[i] = (tokens[i] == 0) ? -INFINITY : 0.0f;
}

// ---------------------------------------------------------------------------
// TF32 tensor-core GEMM. 128x128x32 block tile, 256 thr, 8 warps (2x4),
// warp tile 64x32, mma.sync.m16n8k8.tf32.  C = A * op(B) (+bias) (+res).
//   TB=false: B is [K,N].  TB=true: B is [N,K] (C = A * B^T).
// All dims multiples of 128 (K multiple of 32). Batched via blockIdx.z.
// ---------------------------------------------------------------------------
#define MMA_TF32(d, a, b)                                                     \
    asm volatile(                                                             \
        "mma.sync.aligned.m16n8k8.row.col.f32.tf32.tf32.f32 "                 \
        "{%0,%1,%2,%3},{%4,%5,%6,%7},{%8,%9},{%0,%1,%2,%3};"                  \
        : "+f"((d)[0]), "+f"((d)[1]), "+f"((d)[2]), "+f"((d)[3])              \
        : "r"(__float_as_uint((a)[0])), "r"(__float_as_uint((a)[1])),         \
          "r"(__float_as_uint((a)[2])), "r"(__float_as_uint((a)[3])),         \
          "r"(__float_as_uint((b)[0])), "r"(__float_as_uint((b)[1])))

template <bool TB, bool BIAS, bool RES>
__global__ void __launch_bounds__(256)
gemm_tc(const float* __restrict__ A, const float* __restrict__ B,
        const float* __restrict__ bias, const float* __restrict__ res,
        float* __restrict__ C, int M, int N, int K,
        long sA, long sB, long sC) {
    __shared__ float As[128][36];    // [m][k], bank-conflict-free frag reads
    __shared__ float Bs[32][136];    // [k][n], bank-conflict-free frag reads

    int tid = threadIdx.x;
    int lane = tid & 31, wid = tid >> 5;
    int warpRow = wid >> 2;          // 0..1  (64 rows each)
    int warpCol = wid & 3;           // 0..3  (32 cols each)
    int grp = lane >> 2, qid = lane & 3;

    A += (long)blockIdx.z * sA;
    B += (long)blockIdx.z * sB;
    C += (long)blockIdx.z * sC;
    int row0 = blockIdx.y * 128;
    int col0 = blockIdx.x * 128;

    // A tile loader: thread -> (row, 16-col half)
    int a_r = tid >> 1;
    int a_c = (tid & 1) * 16;
    // B tile loader
    int bnn_k = tid >> 3;            // NN: k row 0..31
    int bnn_c = (tid & 7) * 16;      // NN: 16-col chunk
    int bnt_n = tid >> 1;            // NT: n row 0..127
    int bnt_c = (tid & 1) * 16;      // NT: 16-k chunk

    float acc[4][4][4];
    #pragma unroll
    for (int i = 0; i < 4; i++)
        #pragma unroll
        for (int j = 0; j < 4; j++)
            #pragma unroll
            for (int t = 0; t < 4; t++) acc[i][j][t] = 0.0f;

    for (int k0 = 0; k0 < K; k0 += 32) {
        // ---- load A tile (tf32-rounded at store) ----
        {
            const float4* ap = (const float4*)(A + (long)(row0 + a_r) * K + k0 + a_c);
            #pragma unroll
            for (int e = 0; e < 4; e++) {
                float4 v = ap[e];
                int c = a_c + e * 4;
                As[a_r][c + 0] = tf32r(v.x);
                As[a_r][c + 1] = tf32r(v.y);
                As[a_r][c + 2] = tf32r(v.z);
                As[a_r][c + 3] = tf32r(v.w);
            }
        }
        // ---- load B tile ----
        if (!TB) {
            const float4* bp = (const float4*)(B + (long)(k0 + bnn_k) * N + col0 + bnn_c);
            #pragma unroll
            for (int e = 0; e < 4; e++) {
                float4 v = bp[e];
                int c = bnn_c + e * 4;
                Bs[bnn_k][c + 0] = tf32r(v.x);
                Bs[bnn_k][c + 1] = tf32r(v.y);
                Bs[bnn_k][c + 2] = tf32r(v.z);
                Bs[bnn_k][c + 3] = tf32r(v.w);
            }
        } else {
            const float4* bp = (const float4*)(B + (long)(col0 + bnt_n) * K + k0 + bnt_c);
            #pragma unroll
            for (int e = 0; e < 4; e++) {
                float4 v = bp[e];
                int kk = bnt_c + e * 4;
                Bs[kk + 0][bnt_n] = tf32r(v.x);
                Bs[kk + 1][bnt_n] = tf32r(v.y);
                Bs[kk + 2][bnt_n] = tf32r(v.z);
                Bs[kk + 3][bnt_n] = tf32r(v.w);
            }
        }
        __syncthreads();

        // ---- compute: 4 k-steps of 8 ----
        #pragma unroll
        for (int ks = 0; ks < 4; ks++) {
            float af[4][4];
            #pragma unroll
            for (int i = 0; i < 4; i++) {
                int r = warpRow * 64 + i * 16 + grp;
                int c = ks * 8 + qid;
                af[i][0] = As[r][c];
                af[i][1] = As[r + 8][c];
                af[i][2] = As[r][c + 4];
                af[i][3] = As[r + 8][c + 4];
            }
            float bf[4][2];
            #pragma unroll
            for (int j = 0; j < 4; j++) {
                int n = warpCol * 32 + j * 8 + grp;
                int kk = ks * 8 + qid;
                bf[j][0] = Bs[kk][n];
                bf[j][1] = Bs[kk + 4][n];
            }
            #pragma unroll
            for (int i = 0; i < 4; i++)
                #pragma unroll
                for (int j = 0; j < 4; j++)
                    MMA_TF32(acc[i][j], af[i], bf[j]);
        }
        __syncthreads();
    }

    // ---- epilogue ----
    #pragma unroll
    for (int i = 0; i < 4; i++) {
        int r = row0 + warpRow * 64 + i * 16 + grp;
        #pragma unroll
        for (int j = 0; j < 4; j++) {
            int c = col0 + warpCol * 32 + j * 8 + 2 * qid;
            float2 v0 = make_float2(acc[i][j][0], acc[i][j][1]);   // row r
            float2 v1 = make_float2(acc[i][j][2], acc[i][j][3]);   // row r+8
            if (BIAS) {
                float2 bb = *(const float2*)(bias + c);
                v0.x += bb.x; v0.y += bb.y;
                v1.x += bb.x; v1.y += bb.y;
            }
            if (RES) {
                float2 r0v = *(const float2*)(res + (long)r * N + c);
                float2 r1v = *(const float2*)(res + (long)(r + 8) * N + c);
                v0.x += r0v.x; v0.y += r0v.y;
                v1.x += r1v.x; v1.y += r1v.y;
            }
            *(float2*)(C + (long)r * N + c)       = v0;
            *(float2*)(C + (long)(r + 8) * N + c) = v1;
        }
    }
}

// ---------------------------------------------------------------------------
// Softmax (scale + faithful bh%8 key mask)
// ---------------------------------------------------------------------------
__global__ void __launch_bounds__(256)
softmax_kernel(float* __restrict__ S, const float* __restrict__ nb) {
    int bh = blockIdx.y, q = blockIdx.x, tid = threadIdx.x;
    float* row = S + ((long)bh << 20) + ((long)q << 10);
    const float* nbr = nb + ((bh & 7) << 10);

    float vals[4];
    float mx = -INFINITY;
    #pragma unroll
    for (int i = 0; i < 4; i++) {
        int k = tid + i * 256;
        float v = row[k] * SCALE_F + nbr[k];
        vals[i] = v;
        mx = fmaxf(mx, v);
    }
    mx = blockMax(mx);
    float sum = 0.0f;
    #pragma unroll
    for (int i = 0; i < 4; i++) {
        vals[i] = expf(vals[i] - mx);
        sum += vals[i];
    }
    sum = blockSum(sum);
    float inv = 1.0f / sum;
    #pragma unroll
    for (int i = 0; i < 4; i++) row[tid + i * 256] = vals[i] * inv;
}

// ---------------------------------------------------------------------------
// Pooling + LayerNorm
// ---------------------------------------------------------------------------
__global__ void pool_kernel(const float* __restrict__ r, float* __restrict__ agg) {
    int b = blockIdx.x;
    int d = blockIdx.y * 128 + threadIdx.x;
    const float* base = r + ((long)b << 20) + d;
    float mx = -INFINITY, sm = 0.0f;
    #pragma unroll 4
    for (int l = 0; l < N_L; l++) {
        float v = base[(long)l << 10];
        mx = fmaxf(mx, v);
        sm += v;
    }
    agg[b * 2048 + d]        = mx;
    agg[b * 2048 + 1024 + d] = sm * (1.0f / 1024.0f);
}

__global__ void __launch_bounds__(256)
ln_kernel(const float* __restrict__ agg, const float* __restrict__ gamma,
          const float* __restrict__ beta, float* __restrict__ out) {
    int b = blockIdx.x, tid = threadIdx.x;
    const float* a = agg + b * 2048;
    float s = 0.0f;
    #pragma unroll
    for (int i = 0; i < 8; i++) s += a[tid + i * 256];
    s = blockSum(s);
    float mu = s * (1.0f / 2048.0f);
    float vs = 0.0f;
    #pragma unroll
    for (int i = 0; i < 8; i++) {
        float d = a[tid + i * 256] - mu;
        vs += d * d;
    }
    vs = blockSum(vs);
    float inv = rsqrtf(vs * (1.0f / 2048.0f) + EPS_F);
    #pragma unroll
    for (int i = 0; i < 8; i++) {
        int k = tid + i * 256;
        out[b * 2048 + k] = (a[k] - mu) * inv * gamma[k] + beta[k];
    }
}

// ---------------------------------------------------------------------------
// Launch
// ---------------------------------------------------------------------------
extern "C" void kernel_launch(void* const* d_in, const int* in_sizes, int n_in,
                              void* d_out, int out_size) {
    const int*   tokens = (const int*)  d_in[0];
    const float* emb    = (const float*)d_in[1];
    const float* Wq     = (const float*)d_in[2];
    const float* bq     = (const float*)d_in[3];
    const float* Wk     = (const float*)d_in[4];
    const float* bk     = (const float*)d_in[5];
    const float* Wv     = (const float*)d_in[6];
    const float* bv     = (const float*)d_in[7];
    const float* Wo     = (const float*)d_in[8];
    const float* bo     = (const float*)d_in[9];
    const float* gamma  = (const float*)d_in[10];
    const float* beta   = (const float*)d_in[11];
    float* out = (float*)d_out;

    float *x, *q, *k, *v, *c, *s, *nb, *agg;
    cudaGetSymbolAddress((void**)&x,   g_x);
    cudaGetSymbolAddress((void**)&q,   g_q);
    cudaGetSymbolAddress((void**)&k,   g_k);
    cudaGetSymbolAddress((void**)&v,   g_v);
    cudaGetSymbolAddress((void**)&c,   g_c);
    cudaGetSymbolAddress((void**)&s,   g_s);
    cudaGetSymbolAddress((void**)&nb,  g_nb);
    cudaGetSymbolAddress((void**)&agg, g_agg);

    // 1. embed + mask
    embed_kernel<<<N_B * N_L, 256>>>(tokens, emb, x);
    mask_kernel<<<8, 1024>>>(tokens, nb);

    // 2. Q/K/V projections: [8192,1024] x [1024,1024] + bias   (TF32 MMA)
    dim3 gProj(8, 64, 1);
    gemm_tc<false, true, false><<<gProj, 256>>>(x, Wq, bq, nullptr, q, 8192, 1024, 1024, 0, 0, 0);
    gemm_tc<false, true, false><<<gProj, 256>>>(x, Wk, bk, nullptr, k, 8192, 1024, 1024, 0, 0, 0);
    gemm_tc<false, true, false><<<gProj, 256>>>(x, Wv, bv, nullptr, v, 8192, 1024, 1024, 0, 0, 0);

    // 3. scores = Q K^T  (batched over 64 flat heads)
    dim3 gS(8, 8, 64);
    gemm_tc<true, false, false><<<gS, 256>>>(q, k, nullptr, nullptr, s,
                                             1024, 1024, 128,
                                             131072L, 131072L, 1048576L);

    // 4. softmax rows
    softmax_kernel<<<dim3(1024, 64), 256>>>(s, nb);

    // 5. ctx = P V
    dim3 gPV(1, 8, 64);
    gemm_tc<false, false, false><<<gPV, 256>>>(s, v, nullptr, nullptr, c,
                                               1024, 128, 1024,
                                               1048576L, 131072L, 131072L);

    // 6. r = x + ctx @ Wo + bo   (into g_q, free now)
    gemm_tc<false, true, true><<<gProj, 256>>>(c, Wo, bo, x, q, 8192, 1024, 1024, 0, 0, 0);

    // 7. pool + layernorm
    pool_kernel<<<dim3(8, 8), 128>>>(q, agg);
    ln_kernel<<<8, 256>>>(agg, gamma, beta, out);
}

// round 8
// speedup vs baseline: 2.9821x; 1.4624x over previous
#include <cuda_runtime.h>
#include <math.h>

// Shapes (fixed): B=8, L=1024, D=1024, H=8, DH=128, BH=64
#define N_B    8
#define N_L    1024
#define N_D    1024
#define SCALE_F 0.25f
#define EPS_F   1e-5f

// ---------------------------------------------------------------------------
// Scratch
// ---------------------------------------------------------------------------
__device__ float g_x[8u * 1024u * 1024u];   // embedded input  [B,L,D]
__device__ float g_q[8u * 1024u * 1024u];   // Q, later reused as r = x + out
__device__ float g_k[8u * 1024u * 1024u];   // K
__device__ float g_v[8u * 1024u * 1024u];   // V
__device__ float g_c[8u * 1024u * 1024u];   // ctx
__device__ float g_s[67108864u];            // scores/probs [64,1024,1024]
__device__ float g_nb[8 * 1024];            // -inf mask bias per (batch,key)
__device__ float g_agg[8 * 2048];           // pooled features

// ---------------------------------------------------------------------------
// Helpers
// ---------------------------------------------------------------------------
__device__ __forceinline__ void cpa16(float* dst_smem, const float* src_gmem) {
    unsigned d = (unsigned)__cvta_generic_to_shared(dst_smem);
    asm volatile("cp.async.cg.shared.global [%0], [%1], 16;\n"
                 :: "r"(d), "l"(src_gmem));
}

__device__ __forceinline__ float blockSum(float v) {
    __shared__ float sh[32];
    int lane = threadIdx.x & 31, wid = threadIdx.x >> 5;
    #pragma unroll
    for (int o = 16; o > 0; o >>= 1) v += __shfl_xor_sync(0xffffffffu, v, o);
    if (lane == 0) sh[wid] = v;
    __syncthreads();
    int nw = blockDim.x >> 5;
    float r = (threadIdx.x < (unsigned)nw) ? sh[threadIdx.x] : 0.0f;
    if (wid == 0) {
        #pragma unroll
        for (int o = 16; o > 0; o >>= 1) r += __shfl_xor_sync(0xffffffffu, r, o);
        if (lane == 0) sh[0] = r;
    }
    __syncthreads();
    float out = sh[0];
    __syncthreads();
    return out;
}

__device__ __forceinline__ float blockMax(float v) {
    __shared__ float sh[32];
    int lane = threadIdx.x & 31, wid = threadIdx.x >> 5;
    #pragma unroll
    for (int o = 16; o > 0; o >>= 1) v = fmaxf(v, __shfl_xor_sync(0xffffffffu, v, o));
    if (lane == 0) sh[wid] = v;
    __syncthreads();
    int nw = blockDim.x >> 5;
    float r = (threadIdx.x < (unsigned)nw) ? sh[threadIdx.x] : -INFINITY;
    if (wid == 0) {
        #pragma unroll
        for (int o = 16; o > 0; o >>= 1) r = fmaxf(r, __shfl_xor_sync(0xffffffffu, r, o));
        if (lane == 0) sh[0] = r;
    }
    __syncthreads();
    float out = sh[0];
    __syncthreads();
    return out;
}

// ---------------------------------------------------------------------------
// Embedding gather + mask
// ---------------------------------------------------------------------------
__global__ void embed_kernel(const int* __restrict__ tokens,
                             const float* __restrict__ emb,
                             float* __restrict__ x) {
    int row = blockIdx.x;
    int tok = tokens[row];
    const float4* src = (const float4*)(emb + (long)tok * N_D);
    float4* dst = (float4*)(x + (long)row * N_D);
    dst[threadIdx.x] = src[threadIdx.x];
}

__global__ void mask_kernel(const int* __restrict__ tokens, float* __restrict__ nb) {
    int i = blockIdx.x * blockDim.x + threadIdx.x;
    nb[i] = (tokens[i] == 0) ? -INFINITY : 0.0f;
}

// ---------------------------------------------------------------------------
// MMA: raw f32 registers fed to tf32 MMA (HW truncates low mantissa bits)
// ---------------------------------------------------------------------------
#define MMA_TF32(d, a, b)                                                     \
    asm volatile(                                                             \
        "mma.sync.aligned.m16n8k8.row.col.f32.tf32.tf32.f32 "                 \
        "{%0,%1,%2,%3},{%4,%5,%6,%7},{%8,%9},{%0,%1,%2,%3};"                  \
        : "+f"((d)[0]), "+f"((d)[1]), "+f"((d)[2]), "+f"((d)[3])              \
        : "r"(__float_as_uint((a)[0])), "r"(__float_as_uint((a)[1])),         \
          "r"(__float_as_uint((a)[2])), "r"(__float_as_uint((a)[3])),         \
          "r"(__float_as_uint((b)[0])), "r"(__float_as_uint((b)[1])))

// SMEM tile geometry (padded for conflict-free fragment reads)
#define A_LD    36                       // As row stride (floats)
#define B_LD    136                      // Bs row stride (floats)
#define A_FLTS  (128 * A_LD)             // 4608
#define B_FLTS  (32 * B_LD)              // 4352
#define STG_FLTS (A_FLTS + B_FLTS)       // 8960 floats per stage
#define SMEM_BYTES (2 * STG_FLTS * 4)    // 71680 B

// ---------------------------------------------------------------------------
// NN TF32 GEMM with 2-stage cp.async pipeline.
// 128x128x32 block tile, 256 thr, 8 warps (2x4), warp tile 64x32.
//   C[M,N] = A[M,K] * B[K,N] (+bias) (+res).  Batched via blockIdx.z.
// ---------------------------------------------------------------------------
template <bool BIAS, bool RES>
__global__ void __launch_bounds__(256)
gemm_nn(const float* __restrict__ A, const float* __restrict__ B,
        const float* __restrict__ bias, const float* __restrict__ res,
        float* __restrict__ C, int M, int N, int K,
        long sA, long sB, long sC) {
    extern __shared__ float sm[];

    int tid = threadIdx.x;
    int lane = tid & 31, wid = tid >> 5;
    int warpRow = wid >> 2;          // 0..1
    int warpCol = wid & 3;           // 0..3
    int grp = lane >> 2, qid = lane & 3;

    A += (long)blockIdx.z * sA;
    B += (long)blockIdx.z * sB;
    C += (long)blockIdx.z * sC;
    int row0 = blockIdx.y * 128;
    int col0 = blockIdx.x * 128;

    int KT = K >> 5;

    // async tile loader: A 128x32 (4 f4/thr), B 32x128 (4 f4/thr)
    auto load_tile = [&](int kt, float* Asb, float* Bsb) {
        int k0 = kt << 5;
        #pragma unroll
        for (int p = 0; p < 4; p++) {
            int idx = p * 256 + tid;
            int r = idx >> 3, c4 = (idx & 7) << 2;
            cpa16(Asb + r * A_LD + c4, A + (long)(row0 + r) * K + k0 + c4);
        }
        #pragma unroll
        for (int p = 0; p < 4; p++) {
            int idx = p * 256 + tid;
            int r = idx >> 5, c4 = (idx & 31) << 2;
            cpa16(Bsb + r * B_LD + c4, B + (long)(k0 + r) * N + col0 + c4);
        }
    };

    float acc[4][4][4];
    #pragma unroll
    for (int i = 0; i < 4; i++)
        #pragma unroll
        for (int j = 0; j < 4; j++)
            #pragma unroll
            for (int t = 0; t < 4; t++) acc[i][j][t] = 0.0f;

    // prologue: stage 0
    load_tile(0, sm, sm + A_FLTS);
    asm volatile("cp.async.commit_group;\n" ::);

    for (int kt = 0; kt < KT; kt++) {
        float* Asb = sm + (kt & 1) * STG_FLTS;
        float* Bsb = Asb + A_FLTS;

        if (kt + 1 < KT) {
            float* An = sm + ((kt + 1) & 1) * STG_FLTS;
            load_tile(kt + 1, An, An + A_FLTS);
            asm volatile("cp.async.commit_group;\n" ::);
            asm volatile("cp.async.wait_group 1;\n" ::);
        } else {
            asm volatile("cp.async.wait_group 0;\n" ::);
        }
        __syncthreads();

        #pragma unroll
        for (int ks = 0; ks < 4; ks++) {
            float af[4][4];
            #pragma unroll
            for (int i = 0; i < 4; i++) {
                int r = warpRow * 64 + i * 16 + grp;
                int c = ks * 8 + qid;
                af[i][0] = Asb[r * A_LD + c];
                af[i][1] = Asb[(r + 8) * A_LD + c];
                af[i][2] = Asb[r * A_LD + c + 4];
                af[i][3] = Asb[(r + 8) * A_LD + c + 4];
            }
            float bf[4][2];
            #pragma unroll
            for (int j = 0; j < 4; j++) {
                int n = warpCol * 32 + j * 8 + grp;
                int kk = ks * 8 + qid;
                bf[j][0] = Bsb[kk * B_LD + n];
                bf[j][1] = Bsb[(kk + 4) * B_LD + n];
            }
            #pragma unroll
            for (int i = 0; i < 4; i++)
                #pragma unroll
                for (int j = 0; j < 4; j++)
                    MMA_TF32(acc[i][j], af[i], bf[j]);
        }
        __syncthreads();
    }

    #pragma unroll
    for (int i = 0; i < 4; i++) {
        int r = row0 + warpRow * 64 + i * 16 + grp;
        #pragma unroll
        for (int j = 0; j < 4; j++) {
            int c = col0 + warpCol * 32 + j * 8 + 2 * qid;
            float2 v0 = make_float2(acc[i][j][0], acc[i][j][1]);
            float2 v1 = make_float2(acc[i][j][2], acc[i][j][3]);
            if (BIAS) {
                float2 bb = *(const float2*)(bias + c);
                v0.x += bb.x; v0.y += bb.y;
                v1.x += bb.x; v1.y += bb.y;
            }
            if (RES) {
                float2 r0v = *(const float2*)(res + (long)r * N + c);
                float2 r1v = *(const float2*)(res + (long)(r + 8) * N + c);
                v0.x += r0v.x; v0.y += r0v.y;
                v1.x += r1v.x; v1.y += r1v.y;
            }
            *(float2*)(C + (long)r * N + c)       = v0;
            *(float2*)(C + (long)(r + 8) * N + c) = v1;
        }
    }
}

// ---------------------------------------------------------------------------
// NT TF32 GEMM (C = A * B^T), single-buffered (K=128 only: 4 tiles).
// ---------------------------------------------------------------------------
__global__ void __launch_bounds__(256)
gemm_nt(const float* __restrict__ A, const float* __restrict__ B,
        float* __restrict__ C, int M, int N, int K,
        long sA, long sB, long sC) {
    __shared__ float As[128][A_LD];
    __shared__ float Bs[32][B_LD];

    int tid = threadIdx.x;
    int lane = tid & 31, wid = tid >> 5;
    int warpRow = wid >> 2, warpCol = wid & 3;
    int grp = lane >> 2, qid = lane & 3;

    A += (long)blockIdx.z * sA;
    B += (long)blockIdx.z * sB;
    C += (long)blockIdx.z * sC;
    int row0 = blockIdx.y * 128;
    int col0 = blockIdx.x * 128;

    int a_r = tid >> 1, a_c = (tid & 1) * 16;
    int b_n = tid >> 1, b_c = (tid & 1) * 16;

    float acc[4][4][4];
    #pragma unroll
    for (int i = 0; i < 4; i++)
        #pragma unroll
        for (int j = 0; j < 4; j++)
            #pragma unroll
            for (int t = 0; t < 4; t++) acc[i][j][t] = 0.0f;

    for (int k0 = 0; k0 < K; k0 += 32) {
        const float4* ap = (const float4*)(A + (long)(row0 + a_r) * K + k0 + a_c);
        #pragma unroll
        for (int e = 0; e < 4; e++) {
            float4 v = ap[e];
            *(float4*)&As[a_r][a_c + e * 4] = v;
        }
        const float4* bp = (const float4*)(B + (long)(col0 + b_n) * K + k0 + b_c);
        #pragma unroll
        for (int e = 0; e < 4; e++) {
            float4 v = bp[e];
            int kk = b_c + e * 4;
            Bs[kk + 0][b_n] = v.x;
            Bs[kk + 1][b_n] = v.y;
            Bs[kk + 2][b_n] = v.z;
            Bs[kk + 3][b_n] = v.w;
        }
        __syncthreads();

        #pragma unroll
        for (int ks = 0; ks < 4; ks++) {
            float af[4][4];
            #pragma unroll
            for (int i = 0; i < 4; i++) {
                int r = warpRow * 64 + i * 16 + grp;
                int c = ks * 8 + qid;
                af[i][0] = As[r][c];
                af[i][1] = As[r + 8][c];
                af[i][2] = As[r][c + 4];
                af[i][3] = As[r + 8][c + 4];
            }
            float bf[4][2];
            #pragma unroll
            for (int j = 0; j < 4; j++) {
                int n = warpCol * 32 + j * 8 + grp;
                int kk = ks * 8 + qid;
                bf[j][0] = Bs[kk][n];
                bf[j][1] = Bs[kk + 4][n];
            }
            #pragma unroll
            for (int i = 0; i < 4; i++)
                #pragma unroll
                for (int j = 0; j < 4; j++)
                    MMA_TF32(acc[i][j], af[i], bf[j]);
        }
        __syncthreads();
    }

    #pragma unroll
    for (int i = 0; i < 4; i++) {
        int r = row0 + warpRow * 64 + i * 16 + grp;
        #pragma unroll
        for (int j = 0; j < 4; j++) {
            int c = col0 + warpCol * 32 + j * 8 + 2 * qid;
            *(float2*)(C + (long)r * N + c) =
                make_float2(acc[i][j][0], acc[i][j][1]);
            *(float2*)(C + (long)(r + 8) * N + c) =
                make_float2(acc[i][j][2], acc[i][j][3]);
        }
    }
}

// ---------------------------------------------------------------------------
// Softmax (scale + faithful bh%8 key mask)
// ---------------------------------------------------------------------------
__global__ void __launch_bounds__(256)
softmax_kernel(float* __restrict__ S, const float* __restrict__ nb) {
    int bh = blockIdx.y, q = blockIdx.x, tid = threadIdx.x;
    float* row = S + ((long)bh << 20) + ((long)q << 10);
    const float* nbr = nb + ((bh & 7) << 10);

    float vals[4];
    float mx = -INFINITY;
    #pragma unroll
    for (int i = 0; i < 4; i++) {
        int k = tid + i * 256;
        float v = row[k] * SCALE_F + nbr[k];
        vals[i] = v;
        mx = fmaxf(mx, v);
    }
    mx = blockMax(mx);
    float sum = 0.0f;
    #pragma unroll
    for (int i = 0; i < 4; i++) {
        vals[i] = expf(vals[i] - mx);
        sum += vals[i];
    }
    sum = blockSum(sum);
    float inv = 1.0f / sum;
    #pragma unroll
    for (int i = 0; i < 4; i++) row[tid + i * 256] = vals[i] * inv;
}

// ---------------------------------------------------------------------------
// Pooling + LayerNorm
// ---------------------------------------------------------------------------
__global__ void pool_kernel(const float* __restrict__ r, float* __restrict__ agg) {
    int b = blockIdx.x;
    int d = blockIdx.y * 128 + threadIdx.x;
    const float* base = r + ((long)b << 20) + d;
    float mx = -INFINITY, sm = 0.0f;
    #pragma unroll 4
    for (int l = 0; l < N_L; l++) {
        float v = base[(long)l << 10];
        mx = fmaxf(mx, v);
        sm += v;
    }
    agg[b * 2048 + d]        = mx;
    agg[b * 2048 + 1024 + d] = sm * (1.0f / 1024.0f);
}

__global__ void __launch_bounds__(256)
ln_kernel(const float* __restrict__ agg, const float* __restrict__ gamma,
          const float* __restrict__ beta, float* __restrict__ out) {
    int b = blockIdx.x, tid = threadIdx.x;
    const float* a = agg + b * 2048;
    float s = 0.0f;
    #pragma unroll
    for (int i = 0; i < 8; i++) s += a[tid + i * 256];
    s = blockSum(s);
    float mu = s * (1.0f / 2048.0f);
    float vs = 0.0f;
    #pragma unroll
    for (int i = 0; i < 8; i++) {
        float d = a[tid + i * 256] - mu;
        vs += d * d;
    }
    vs = blockSum(vs);
    float inv = rsqrtf(vs * (1.0f / 2048.0f) + EPS_F);
    #pragma unroll
    for (int i = 0; i < 8; i++) {
        int k = tid + i * 256;
        out[b * 2048 + k] = (a[k] - mu) * inv * gamma[k] + beta[k];
    }
}

// ---------------------------------------------------------------------------
// Launch
// ---------------------------------------------------------------------------
extern "C" void kernel_launch(void* const* d_in, const int* in_sizes, int n_in,
                              void* d_out, int out_size) {
    const int*   tokens = (const int*)  d_in[0];
    const float* emb    = (const float*)d_in[1];
    const float* Wq     = (const float*)d_in[2];
    const float* bq     = (const float*)d_in[3];
    const float* Wk     = (const float*)d_in[4];
    const float* bk     = (const float*)d_in[5];
    const float* Wv     = (const float*)d_in[6];
    const float* bv     = (const float*)d_in[7];
    const float* Wo     = (const float*)d_in[8];
    const float* bo     = (const float*)d_in[9];
    const float* gamma  = (const float*)d_in[10];
    const float* beta   = (const float*)d_in[11];
    float* out = (float*)d_out;

    float *x, *q, *k, *v, *c, *s, *nb, *agg;
    cudaGetSymbolAddress((void**)&x,   g_x);
    cudaGetSymbolAddress((void**)&q,   g_q);
    cudaGetSymbolAddress((void**)&k,   g_k);
    cudaGetSymbolAddress((void**)&v,   g_v);
    cudaGetSymbolAddress((void**)&c,   g_c);
    cudaGetSymbolAddress((void**)&s,   g_s);
    cudaGetSymbolAddress((void**)&nb,  g_nb);
    cudaGetSymbolAddress((void**)&agg, g_agg);

    // allow 70KB dynamic smem for the async GEMM variants (idempotent)
    cudaFuncSetAttribute(gemm_nn<true,  false>,
                         cudaFuncAttributeMaxDynamicSharedMemorySize, SMEM_BYTES);
    cudaFuncSetAttribute(gemm_nn<false, false>,
                         cudaFuncAttributeMaxDynamicSharedMemorySize, SMEM_BYTES);
    cudaFuncSetAttribute(gemm_nn<true,  true>,
                         cudaFuncAttributeMaxDynamicSharedMemorySize, SMEM_BYTES);

    // 1. embed + mask
    embed_kernel<<<N_B * N_L, 256>>>(tokens, emb, x);
    mask_kernel<<<8, 1024>>>(tokens, nb);

    // 2. Q/K/V projections (async-pipelined TF32 MMA)
    dim3 gProj(8, 64, 1);
    gemm_nn<true,  false><<<gProj, 256, SMEM_BYTES>>>(x, Wq, bq, nullptr, q, 8192, 1024, 1024, 0, 0, 0);
    gemm_nn<true,  false><<<gProj, 256, SMEM_BYTES>>>(x, Wk, bk, nullptr, k, 8192, 1024, 1024, 0, 0, 0);
    gemm_nn<true,  false><<<gProj, 256, SMEM_BYTES>>>(x, Wv, bv, nullptr, v, 8192, 1024, 1024, 0, 0, 0);

    // 3. scores = Q K^T  (batched over 64 flat heads, K=128)
    dim3 gS(8, 8, 64);
    gemm_nt<<<gS, 256>>>(q, k, s, 1024, 1024, 128,
                         131072L, 131072L, 1048576L);

    // 4. softmax rows
    softmax_kernel<<<dim3(1024, 64), 256>>>(s, nb);

    // 5. ctx = P V  (async-pipelined, K=1024)
    dim3 gPV(1, 8, 64);
    gemm_nn<false, false><<<gPV, 256, SMEM_BYTES>>>(s, v, nullptr, nullptr, c,
                                                    1024, 128, 1024,
                                                    1048576L, 131072L, 131072L);

    // 6. r = x + ctx @ Wo + bo
    gemm_nn<true, true><<<gProj, 256, SMEM_BYTES>>>(c, Wo, bo, x, q, 8192, 1024, 1024, 0, 0, 0);

    // 7. pool + layernorm
    pool_kernel<<<dim3(8, 8), 128>>>(q, agg);
    ln_kernel<<<8, 256>>>(agg, gamma, beta, out);
}

// round 9
// speedup vs baseline: 4.5558x; 1.5277x over previous
#include <cuda_runtime.h>
#include <cuda_bf16.h>
#include <math.h>

// Shapes (fixed): B=8, L=1024, D=1024, H=8, DH=128, BH=64
#define N_B    8
#define N_L    1024
#define N_D    1024
#define SCALE_F 0.25f
#define EPS_F   1e-5f

// ---------------------------------------------------------------------------
// Scratch
// ---------------------------------------------------------------------------
__device__ float g_x[8u * 1024u * 1024u];     // embedded input (f32, residual)
__device__ float g_r[8u * 1024u * 1024u];     // r = x + out (f32)
__device__ float g_s[67108864u];              // scores [64,1024,1024] f32
__device__ float g_nb[8 * 1024];              // -inf mask bias
__device__ float g_agg[8 * 2048];             // pooled

__device__ __nv_bfloat16 g_xb[8u * 1024u * 1024u];   // x bf16
__device__ __nv_bfloat16 g_qb[8u * 1024u * 1024u];   // Q bf16
__device__ __nv_bfloat16 g_kb[8u * 1024u * 1024u];   // K bf16
__device__ __nv_bfloat16 g_vb[8u * 1024u * 1024u];   // V bf16
__device__ __nv_bfloat16 g_cb[8u * 1024u * 1024u];   // ctx bf16
__device__ __nv_bfloat16 g_pb[67108864u];            // probs bf16
__device__ __nv_bfloat16 g_wq[1024 * 1024];
__device__ __nv_bfloat16 g_wk[1024 * 1024];
__device__ __nv_bfloat16 g_wv[1024 * 1024];
__device__ __nv_bfloat16 g_wo[1024 * 1024];

// ---------------------------------------------------------------------------
// Helpers
// ---------------------------------------------------------------------------
__device__ __forceinline__ void cpa16(void* dst_smem, const void* src_gmem) {
    unsigned d = (unsigned)__cvta_generic_to_shared(dst_smem);
    asm volatile("cp.async.cg.shared.global [%0], [%1], 16;\n"
                 :: "r"(d), "l"(src_gmem));
}

__device__ __forceinline__ float blockSum(float v) {
    __shared__ float sh[32];
    int lane = threadIdx.x & 31, wid = threadIdx.x >> 5;
    #pragma unroll
    for (int o = 16; o > 0; o >>= 1) v += __shfl_xor_sync(0xffffffffu, v, o);
    if (lane == 0) sh[wid] = v;
    __syncthreads();
    int nw = blockDim.x >> 5;
    float r = (threadIdx.x < (unsigned)nw) ? sh[threadIdx.x] : 0.0f;
    if (wid == 0) {
        #pragma unroll
        for (int o = 16; o > 0; o >>= 1) r += __shfl_xor_sync(0xffffffffu, r, o);
        if (lane == 0) sh[0] = r;
    }
    __syncthreads();
    float out = sh[0];
    __syncthreads();
    return out;
}

__device__ __forceinline__ float blockMax(float v) {
    __shared__ float sh[32];
    int lane = threadIdx.x & 31, wid = threadIdx.x >> 5;
    #pragma unroll
    for (int o = 16; o > 0; o >>= 1) v = fmaxf(v, __shfl_xor_sync(0xffffffffu, v, o));
    if (lane == 0) sh[wid] = v;
    __syncthreads();
    int nw = blockDim.x >> 5;
    float r = (threadIdx.x < (unsigned)nw) ? sh[threadIdx.x] : -INFINITY;
    if (wid == 0) {
        #pragma unroll
        for (int o = 16; o > 0; o >>= 1) r = fmaxf(r, __shfl_xor_sync(0xffffffffu, r, o));
        if (lane == 0) sh[0] = r;
    }
    __syncthreads();
    float out = sh[0];
    __syncthreads();
    return out;
}

// ---------------------------------------------------------------------------
// Embedding (writes f32 + bf16 copies) + mask + f32->bf16 weight convert
// ---------------------------------------------------------------------------
__global__ void embed_kernel(const int* __restrict__ tokens,
                             const float* __restrict__ emb,
                             float* __restrict__ x,
                             __nv_bfloat16* __restrict__ xb) {
    int row = blockIdx.x;
    int tok = tokens[row];
    float4 v = ((const float4*)(emb + (long)tok * N_D))[threadIdx.x];
    ((float4*)(x + (long)row * N_D))[threadIdx.x] = v;
    __nv_bfloat162* db = (__nv_bfloat162*)(xb + (long)row * N_D);
    db[2 * threadIdx.x]     = __nv_bfloat162(__float2bfloat16(v.x), __float2bfloat16(v.y));
    db[2 * threadIdx.x + 1] = __nv_bfloat162(__float2bfloat16(v.z), __float2bfloat16(v.w));
}

__global__ void mask_kernel(const int* __restrict__ tokens, float* __restrict__ nb) {
    int i = blockIdx.x * blockDim.x + threadIdx.x;
    nb[i] = (tokens[i] == 0) ? -INFINITY : 0.0f;
}

__global__ void conv_kernel(const float* __restrict__ src, __nv_bfloat16* __restrict__ dst) {
    int i = blockIdx.x * blockDim.x + threadIdx.x;   // over pairs
    float2 v = ((const float2*)src)[i];
    ((__nv_bfloat162*)dst)[i] = __nv_bfloat162(__float2bfloat16(v.x), __float2bfloat16(v.y));
}

// ---------------------------------------------------------------------------
// bf16 MMA + ldmatrix
// ---------------------------------------------------------------------------
#define MMA_BF16(d, a, b)                                                     \
    asm volatile(                                                             \
        "mma.sync.aligned.m16n8k16.row.col.f32.bf16.bf16.f32 "                \
        "{%0,%1,%2,%3},{%4,%5,%6,%7},{%8,%9},{%0,%1,%2,%3};"                  \
        : "+f"((d)[0]), "+f"((d)[1]), "+f"((d)[2]), "+f"((d)[3])              \
        : "r"((a)[0]), "r"((a)[1]), "r"((a)[2]), "r"((a)[3]),                 \
          "r"((b)[0]), "r"((b)[1]))

#define LDSM_X4(r0, r1, r2, r3, addr)                                         \
    asm volatile("ldmatrix.sync.aligned.m8n8.x4.shared.b16 {%0,%1,%2,%3}, [%4];" \
                 : "=r"(r0), "=r"(r1), "=r"(r2), "=r"(r3) : "r"(addr))

#define LDSM_X4T(r0, r1, r2, r3, addr)                                        \
    asm volatile("ldmatrix.sync.aligned.m8n8.x4.trans.shared.b16 {%0,%1,%2,%3}, [%4];" \
                 : "=r"(r0), "=r"(r1), "=r"(r2), "=r"(r3) : "r"(addr))

// SMEM geometry (halves).  A tile 128x32 (row stride 40), B tile:
//   NN: 32x128 (stride 136)   NT: 128x32 (stride 40)
#define A_LDH   40
#define BNN_LDH 136
#define BNT_LDH 40
#define A_H     (128 * A_LDH)          // 5120
#define B_H     5120                   // max(32*136=4352, 128*40=5120)
#define STG_H   (A_H + B_H)            // 10240 halves = 20480 B
#define NSTG    3
#define SMEM_BYTES (NSTG * STG_H * 2)  // 61440 B

// ---------------------------------------------------------------------------
// bf16 tensor GEMM, 128x128x32 block tile, 256 thr, warp tile 64x32,
// 3-stage cp.async pipeline, ldmatrix fragments.
//   BT=0: B[K,N] (NN, ldmatrix.trans)   BT=1: B[N,K] (C = A*B^T)
//   OBF:  output bf16 (else f32).  BIAS/RES: f32 epilogue adds.
// ---------------------------------------------------------------------------
template <bool BT, bool BIAS, bool RES, bool OBF>
__global__ void __launch_bounds__(256)
gemm_bf(const __nv_bfloat16* __restrict__ A, const __nv_bfloat16* __restrict__ B,
        const float* __restrict__ bias, const float* __restrict__ res,
        void* __restrict__ Cv, int M, int N, int K,
        long sA, long sB, long sC) {
    extern __shared__ __nv_bfloat16 sm[];

    int tid = threadIdx.x;
    int lane = tid & 31, wid = tid >> 5;
    int warpRow = wid >> 2;          // 0..1
    int warpCol = wid & 3;           // 0..3
    int grp = lane >> 2, qid = lane & 3;

    A += (long)blockIdx.z * sA;
    B += (long)blockIdx.z * sB;
    int row0 = blockIdx.y * 128;
    int col0 = blockIdx.x * 128;
    int KT = K >> 5;

    auto load_tile = [&](int kt, __nv_bfloat16* Asb, __nv_bfloat16* Bsb) {
        int k0 = kt << 5;
        // A: 128x32, 2 chunks of 16B per thread
        #pragma unroll
        for (int p = 0; p < 2; p++) {
            int idx = p * 256 + tid;
            int r = idx >> 2, cc = (idx & 3) << 3;
            cpa16(Asb + r * A_LDH + cc, A + (long)(row0 + r) * K + k0 + cc);
        }
        if (!BT) {   // B[K,N]: 32x128 tile
            #pragma unroll
            for (int p = 0; p < 2; p++) {
                int idx = p * 256 + tid;
                int r = idx >> 4, cc = (idx & 15) << 3;
                cpa16(Bsb + r * BNN_LDH + cc, B + (long)(k0 + r) * N + col0 + cc);
            }
        } else {     // B[N,K]: 128x32 tile
            #pragma unroll
            for (int p = 0; p < 2; p++) {
                int idx = p * 256 + tid;
                int r = idx >> 2, cc = (idx & 3) << 3;
                cpa16(Bsb + r * BNT_LDH + cc, B + (long)(col0 + r) * K + k0 + cc);
            }
        }
    };

    float acc[4][4][4];
    #pragma unroll
    for (int i = 0; i < 4; i++)
        #pragma unroll
        for (int j = 0; j < 4; j++)
            #pragma unroll
            for (int t = 0; t < 4; t++) acc[i][j][t] = 0.0f;

    // prologue: stages 0,1
    load_tile(0, sm, sm + A_H);
    asm volatile("cp.async.commit_group;\n" ::);
    if (KT > 1) load_tile(1, sm + STG_H, sm + STG_H + A_H);
    asm volatile("cp.async.commit_group;\n" ::);

    for (int kt = 0; kt < KT; kt++) {
        __nv_bfloat16* Asb = sm + (kt % NSTG) * STG_H;
        __nv_bfloat16* Bsb = Asb + A_H;

        if (kt + 2 < KT) {
            __nv_bfloat16* An = sm + ((kt + 2) % NSTG) * STG_H;
            load_tile(kt + 2, An, An + A_H);
        }
        asm volatile("cp.async.commit_group;\n" ::);
        asm volatile("cp.async.wait_group 2;\n" ::);
        __syncthreads();

        unsigned AsU = (unsigned)__cvta_generic_to_shared(Asb);
        unsigned BsU = (unsigned)__cvta_generic_to_shared(Bsb);

        #pragma unroll
        for (int ks = 0; ks < 2; ks++) {
            int k0h = ks * 16;
            unsigned a[4][4];
            #pragma unroll
            for (int i = 0; i < 4; i++) {
                int r = warpRow * 64 + i * 16 + (lane & 15);
                unsigned ad = AsU + (r * A_LDH + k0h + ((lane >> 4) << 3)) * 2;
                LDSM_X4(a[i][0], a[i][1], a[i][2], a[i][3], ad);
            }
            unsigned b[4][2];
            #pragma unroll
            for (int j2 = 0; j2 < 2; j2++) {
                int n0 = warpCol * 32 + j2 * 16;
                if (!BT) {
                    int r = k0h + (((lane >> 3) & 1) << 3) + (lane & 7);
                    int c = n0 + ((lane >> 4) << 3);
                    unsigned ad = BsU + (r * BNN_LDH + c) * 2;
                    LDSM_X4T(b[2 * j2][0], b[2 * j2][1], b[2 * j2 + 1][0], b[2 * j2 + 1][1], ad);
                } else {
                    int r = n0 + ((lane >> 4) << 3) + (lane & 7);
                    int c = k0h + (((lane >> 3) & 1) << 3);
                    unsigned ad = BsU + (r * BNT_LDH + c) * 2;
                    LDSM_X4(b[2 * j2][0], b[2 * j2][1], b[2 * j2 + 1][0], b[2 * j2 + 1][1], ad);
                }
            }
            #pragma unroll
            for (int i = 0; i < 4; i++)
                #pragma unroll
                for (int j = 0; j < 4; j++)
                    MMA_BF16(acc[i][j], a[i], b[j]);
        }
        __syncthreads();
    }

    // epilogue
    #pragma unroll
    for (int i = 0; i < 4; i++) {
        int r = row0 + warpRow * 64 + i * 16 + grp;
        #pragma unroll
        for (int j = 0; j < 4; j++) {
            int c = col0 + warpCol * 32 + j * 8 + 2 * qid;
            float2 v0 = make_float2(acc[i][j][0], acc[i][j][1]);
            float2 v1 = make_float2(acc[i][j][2], acc[i][j][3]);
            if (BIAS) {
                float2 bb = *(const float2*)(bias + c);
                v0.x += bb.x; v0.y += bb.y;
                v1.x += bb.x; v1.y += bb.y;
            }
            if (RES) {
                const float* rp = res + (long)blockIdx.z * sC;
                float2 r0v = *(const float2*)(rp + (long)r * N + c);
                float2 r1v = *(const float2*)(rp + (long)(r + 8) * N + c);
                v0.x += r0v.x; v0.y += r0v.y;
                v1.x += r1v.x; v1.y += r1v.y;
            }
            if (OBF) {
                __nv_bfloat16* C = (__nv_bfloat16*)Cv + (long)blockIdx.z * sC;
                *(__nv_bfloat162*)(C + (long)r * N + c) =
                    __nv_bfloat162(__float2bfloat16(v0.x), __float2bfloat16(v0.y));
                *(__nv_bfloat162*)(C + (long)(r + 8) * N + c) =
                    __nv_bfloat162(__float2bfloat16(v1.x), __float2bfloat16(v1.y));
            } else {
                float* C = (float*)Cv + (long)blockIdx.z * sC;
                *(float2*)(C + (long)r * N + c)       = v0;
                *(float2*)(C + (long)(r + 8) * N + c) = v1;
            }
        }
    }
}

// ---------------------------------------------------------------------------
// Softmax: f32 scores in, bf16 probs out (scale + faithful bh%8 key mask)
// ---------------------------------------------------------------------------
__global__ void __launch_bounds__(256)
softmax_kernel(const float* __restrict__ S, const float* __restrict__ nb,
               __nv_bfloat16* __restrict__ P) {
    int bh = blockIdx.y, q = blockIdx.x, tid = threadIdx.x;
    const float* row = S + ((long)bh << 20) + ((long)q << 10);
    __nv_bfloat16* prow = P + ((long)bh << 20) + ((long)q << 10);
    const float* nbr = nb + ((bh & 7) << 10);

    float vals[4];
    float mx = -INFINITY;
    #pragma unroll
    for (int i = 0; i < 4; i++) {
        int k = tid + i * 256;
        float v = row[k] * SCALE_F + nbr[k];
        vals[i] = v;
        mx = fmaxf(mx, v);
    }
    mx = blockMax(mx);
    float sum = 0.0f;
    #pragma unroll
    for (int i = 0; i < 4; i++) {
        vals[i] = expf(vals[i] - mx);
        sum += vals[i];
    }
    sum = blockSum(sum);
    float inv = 1.0f / sum;
    #pragma unroll
    for (int i = 0; i < 4; i++)
        prow[tid + i * 256] = __float2bfloat16(vals[i] * inv);
}

// ---------------------------------------------------------------------------
// Pooling + LayerNorm
// ---------------------------------------------------------------------------
__global__ void pool_kernel(const float* __restrict__ r, float* __restrict__ agg) {
    int b = blockIdx.x;
    int d = blockIdx.y * 128 + threadIdx.x;
    const float* base = r + ((long)b << 20) + d;
    float mx = -INFINITY, sm = 0.0f;
    #pragma unroll 4
    for (int l = 0; l < N_L; l++) {
        float v = base[(long)l << 10];
        mx = fmaxf(mx, v);
        sm += v;
    }
    agg[b * 2048 + d]        = mx;
    agg[b * 2048 + 1024 + d] = sm * (1.0f / 1024.0f);
}

__global__ void __launch_bounds__(256)
ln_kernel(const float* __restrict__ agg, const float* __restrict__ gamma,
          const float* __restrict__ beta, float* __restrict__ out) {
    int b = blockIdx.x, tid = threadIdx.x;
    const float* a = agg + b * 2048;
    float s = 0.0f;
    #pragma unroll
    for (int i = 0; i < 8; i++) s += a[tid + i * 256];
    s = blockSum(s);
    float mu = s * (1.0f / 2048.0f);
    float vs = 0.0f;
    #pragma unroll
    for (int i = 0; i < 8; i++) {
        float d = a[tid + i * 256] - mu;
        vs += d * d;
    }
    vs = blockSum(vs);
    float inv = rsqrtf(vs * (1.0f / 2048.0f) + EPS_F);
    #pragma unroll
    for (int i = 0; i < 8; i++) {
        int k = tid + i * 256;
        out[b * 2048 + k] = (a[k] - mu) * inv * gamma[k] + beta[k];
    }
}

// ---------------------------------------------------------------------------
// Launch
// ---------------------------------------------------------------------------
extern "C" void kernel_launch(void* const* d_in, const int* in_sizes, int n_in,
                              void* d_out, int out_size) {
    const int*   tokens = (const int*)  d_in[0];
    const float* emb    = (const float*)d_in[1];
    const float* Wq     = (const float*)d_in[2];
    const float* bq     = (const float*)d_in[3];
    const float* Wk     = (const float*)d_in[4];
    const float* bk     = (const float*)d_in[5];
    const float* Wv     = (const float*)d_in[6];
    const float* bv     = (const float*)d_in[7];
    const float* Wo     = (const float*)d_in[8];
    const float* bo     = (const float*)d_in[9];
    const float* gamma  = (const float*)d_in[10];
    const float* beta   = (const float*)d_in[11];
    float* out = (float*)d_out;

    float *x, *r, *s, *nb, *agg;
    __nv_bfloat16 *xb, *qb, *kb, *vb, *cb, *pb, *wq, *wk, *wv, *wo;
    cudaGetSymbolAddress((void**)&x,   g_x);
    cudaGetSymbolAddress((void**)&r,   g_r);
    cudaGetSymbolAddress((void**)&s,   g_s);
    cudaGetSymbolAddress((void**)&nb,  g_nb);
    cudaGetSymbolAddress((void**)&agg, g_agg);
    cudaGetSymbolAddress((void**)&xb,  g_xb);
    cudaGetSymbolAddress((void**)&qb,  g_qb);
    cudaGetSymbolAddress((void**)&kb,  g_kb);
    cudaGetSymbolAddress((void**)&vb,  g_vb);
    cudaGetSymbolAddress((void**)&cb,  g_cb);
    cudaGetSymbolAddress((void**)&pb,  g_pb);
    cudaGetSymbolAddress((void**)&wq,  g_wq);
    cudaGetSymbolAddress((void**)&wk,  g_wk);
    cudaGetSymbolAddress((void**)&wv,  g_wv);
    cudaGetSymbolAddress((void**)&wo,  g_wo);

    cudaFuncSetAttribute(gemm_bf<false, true,  false, true>,
                         cudaFuncAttributeMaxDynamicSharedMemorySize, SMEM_BYTES);
    cudaFuncSetAttribute(gemm_bf<true,  false, false, false>,
                         cudaFuncAttributeMaxDynamicSharedMemorySize, SMEM_BYTES);
    cudaFuncSetAttribute(gemm_bf<false, false, false, true>,
                         cudaFuncAttributeMaxDynamicSharedMemorySize, SMEM_BYTES);
    cudaFuncSetAttribute(gemm_bf<false, true,  true,  false>,
                         cudaFuncAttributeMaxDynamicSharedMemorySize, SMEM_BYTES);

    // 1. embed (f32 + bf16), mask, weight conversion
    embed_kernel<<<N_B * N_L, 256>>>(tokens, emb, x, xb);
    mask_kernel<<<8, 1024>>>(tokens, nb);
    conv_kernel<<<2048, 256>>>(Wq, wq);
    conv_kernel<<<2048, 256>>>(Wk, wk);
    conv_kernel<<<2048, 256>>>(Wv, wv);
    conv_kernel<<<2048, 256>>>(Wo, wo);

    // 2. Q/K/V projections -> bf16
    dim3 gProj(8, 64, 1);
    gemm_bf<false, true, false, true><<<gProj, 256, SMEM_BYTES>>>(
        xb, wq, bq, nullptr, qb, 8192, 1024, 1024, 0, 0, 0);
    gemm_bf<false, true, false, true><<<gProj, 256, SMEM_BYTES>>>(
        xb, wk, bk, nullptr, kb, 8192, 1024, 1024, 0, 0, 0);
    gemm_bf<false, true, false, true><<<gProj, 256, SMEM_BYTES>>>(
        xb, wv, bv, nullptr, vb, 8192, 1024, 1024, 0, 0, 0);

    // 3. scores = Q K^T (64 flat heads, K=128) -> f32
    dim3 gS(8, 8, 64);
    gemm_bf<true, false, false, false><<<gS, 256, SMEM_BYTES>>>(
        qb, kb, nullptr, nullptr, s, 1024, 1024, 128,
        131072L, 131072L, 1048576L);

    // 4. softmax -> bf16 probs
    softmax_kernel<<<dim3(1024, 64), 256>>>(s, nb, pb);

    // 5. ctx = P V -> bf16
    dim3 gPV(1, 8, 64);
    gemm_bf<false, false, false, true><<<gPV, 256, SMEM_BYTES>>>(
        pb, vb, nullptr, nullptr, cb, 1024, 128, 1024,
        1048576L, 131072L, 131072L);

    // 6. r = x + ctx @ Wo + bo -> f32
    gemm_bf<false, true, true, false><<<gProj, 256, SMEM_BYTES>>>(
        cb, wo, bo, x, r, 8192, 1024, 1024, 0, 0, 0);

    // 7. pool + layernorm
    pool_kernel<<<dim3(8, 8), 128>>>(r, agg);
    ln_kernel<<<8, 256>>>(agg, gamma, beta, out);
}

// round 10
// speedup vs baseline: 5.4393x; 1.1939x over previous
#include <cuda_runtime.h>
#include <cuda_bf16.h>
#include <math.h>

// Shapes (fixed): B=8, L=1024, D=1024, H=8, DH=128, BH=64
#define N_B    8
#define N_L    1024
#define N_D    1024
#define SCALE_F 0.25f
#define EPS_F   1e-5f
#define LOG2E_F 1.4426950408889634f

// ---------------------------------------------------------------------------
// Scratch
// ---------------------------------------------------------------------------
__device__ float g_x[8u * 1024u * 1024u];     // embedded input (f32, residual)
__device__ float g_r[8u * 1024u * 1024u];     // r = x + out (f32)
__device__ float g_nb[8 * 1024];              // -inf mask bias
__device__ float g_agg[8 * 2048];             // pooled

__device__ __nv_bfloat16 g_xb[8u * 1024u * 1024u];   // x bf16
__device__ __nv_bfloat16 g_qb[8u * 1024u * 1024u];   // Q bf16
__device__ __nv_bfloat16 g_kb[8u * 1024u * 1024u];   // K bf16
__device__ __nv_bfloat16 g_vb[8u * 1024u * 1024u];   // V bf16
__device__ __nv_bfloat16 g_cb[8u * 1024u * 1024u];   // ctx bf16
__device__ __nv_bfloat16 g_wq[1024 * 1024];
__device__ __nv_bfloat16 g_wk[1024 * 1024];
__device__ __nv_bfloat16 g_wv[1024 * 1024];
__device__ __nv_bfloat16 g_wo[1024 * 1024];

// ---------------------------------------------------------------------------
// Helpers
// ---------------------------------------------------------------------------
__device__ __forceinline__ void cpa16(void* dst_smem, const void* src_gmem) {
    unsigned d = (unsigned)__cvta_generic_to_shared(dst_smem);
    asm volatile("cp.async.cg.shared.global [%0], [%1], 16;\n"
                 :: "r"(d), "l"(src_gmem));
}

__device__ __forceinline__ float blockSum(float v) {
    __shared__ float sh[32];
    int lane = threadIdx.x & 31, wid = threadIdx.x >> 5;
    #pragma unroll
    for (int o = 16; o > 0; o >>= 1) v += __shfl_xor_sync(0xffffffffu, v, o);
    if (lane == 0) sh[wid] = v;
    __syncthreads();
    int nw = blockDim.x >> 5;
    float r = (threadIdx.x < (unsigned)nw) ? sh[threadIdx.x] : 0.0f;
    if (wid == 0) {
        #pragma unroll
        for (int o = 16; o > 0; o >>= 1) r += __shfl_xor_sync(0xffffffffu, r, o);
        if (lane == 0) sh[0] = r;
    }
    __syncthreads();
    float out = sh[0];
    __syncthreads();
    return out;
}

// ---------------------------------------------------------------------------
// Embedding (f32 + bf16) + mask + weight convert
// ---------------------------------------------------------------------------
__global__ void embed_kernel(const int* __restrict__ tokens,
                             const float* __restrict__ emb,
                             float* __restrict__ x,
                             __nv_bfloat16* __restrict__ xb) {
    int row = blockIdx.x;
    int tok = tokens[row];
    float4 v = ((const float4*)(emb + (long)tok * N_D))[threadIdx.x];
    ((float4*)(x + (long)row * N_D))[threadIdx.x] = v;
    __nv_bfloat162* db = (__nv_bfloat162*)(xb + (long)row * N_D);
    db[2 * threadIdx.x]     = __nv_bfloat162(__float2bfloat16(v.x), __float2bfloat16(v.y));
    db[2 * threadIdx.x + 1] = __nv_bfloat162(__float2bfloat16(v.z), __float2bfloat16(v.w));
}

__global__ void mask_kernel(const int* __restrict__ tokens, float* __restrict__ nb) {
    int i = blockIdx.x * blockDim.x + threadIdx.x;
    nb[i] = (tokens[i] == 0) ? -INFINITY : 0.0f;
}

__global__ void conv_kernel(const float* __restrict__ src, __nv_bfloat16* __restrict__ dst) {
    int i = blockIdx.x * blockDim.x + threadIdx.x;
    float2 v = ((const float2*)src)[i];
    ((__nv_bfloat162*)dst)[i] = __nv_bfloat162(__float2bfloat16(v.x), __float2bfloat16(v.y));
}

// ---------------------------------------------------------------------------
// bf16 MMA + ldmatrix
// ---------------------------------------------------------------------------
#define MMA_BF16(d, a, b)                                                     \
    asm volatile(                                                             \
        "mma.sync.aligned.m16n8k16.row.col.f32.bf16.bf16.f32 "                \
        "{%0,%1,%2,%3},{%4,%5,%6,%7},{%8,%9},{%0,%1,%2,%3};"                  \
        : "+f"((d)[0]), "+f"((d)[1]), "+f"((d)[2]), "+f"((d)[3])              \
        : "r"((a)[0]), "r"((a)[1]), "r"((a)[2]), "r"((a)[3]),                 \
          "r"((b)[0]), "r"((b)[1]))

#define LDSM_X4(r0, r1, r2, r3, addr)                                         \
    asm volatile("ldmatrix.sync.aligned.m8n8.x4.shared.b16 {%0,%1,%2,%3}, [%4];" \
                 : "=r"(r0), "=r"(r1), "=r"(r2), "=r"(r3) : "r"(addr))

#define LDSM_X4T(r0, r1, r2, r3, addr)                                        \
    asm volatile("ldmatrix.sync.aligned.m8n8.x4.trans.shared.b16 {%0,%1,%2,%3}, [%4];" \
                 : "=r"(r0), "=r"(r1), "=r"(r2), "=r"(r3) : "r"(addr))

// ---------------------------------------------------------------------------
// GEMM SMEM geometry
// ---------------------------------------------------------------------------
#define A_LDH   40
#define BNN_LDH 136
#define A_H     (128 * A_LDH)
#define B_H     5120
#define STG_H   (A_H + B_H)
#define NSTG    3
#define SMEM_BYTES (NSTG * STG_H * 2)

// ---------------------------------------------------------------------------
// bf16 NN tensor GEMM (projections + Wo): 128x128x32 tile, 3-stage cp.async.
// ---------------------------------------------------------------------------
template <bool BIAS, bool RES, bool OBF>
__global__ void __launch_bounds__(256)
gemm_bf(const __nv_bfloat16* __restrict__ A, const __nv_bfloat16* __restrict__ B,
        const float* __restrict__ bias, const float* __restrict__ res,
        void* __restrict__ Cv, int M, int N, int K) {
    extern __shared__ __nv_bfloat16 sm[];

    int tid = threadIdx.x;
    int lane = tid & 31, wid = tid >> 5;
    int warpRow = wid >> 2, warpCol = wid & 3;
    int grp = lane >> 2, qid = lane & 3;

    int row0 = blockIdx.y * 128;
    int col0 = blockIdx.x * 128;
    int KT = K >> 5;

    auto load_tile = [&](int kt, __nv_bfloat16* Asb, __nv_bfloat16* Bsb) {
        int k0 = kt << 5;
        #pragma unroll
        for (int p = 0; p < 2; p++) {
            int idx = p * 256 + tid;
            int r = idx >> 2, cc = (idx & 3) << 3;
            cpa16(Asb + r * A_LDH + cc, A + (long)(row0 + r) * K + k0 + cc);
        }
        #pragma unroll
        for (int p = 0; p < 2; p++) {
            int idx = p * 256 + tid;
            int r = idx >> 4, cc = (idx & 15) << 3;
            cpa16(Bsb + r * BNN_LDH + cc, B + (long)(k0 + r) * N + col0 + cc);
        }
    };

    float acc[4][4][4];
    #pragma unroll
    for (int i = 0; i < 4; i++)
        #pragma unroll
        for (int j = 0; j < 4; j++)
            #pragma unroll
            for (int t = 0; t < 4; t++) acc[i][j][t] = 0.0f;

    load_tile(0, sm, sm + A_H);
    asm volatile("cp.async.commit_group;\n" ::);
    if (KT > 1) load_tile(1, sm + STG_H, sm + STG_H + A_H);
    asm volatile("cp.async.commit_group;\n" ::);

    for (int kt = 0; kt < KT; kt++) {
        __nv_bfloat16* Asb = sm + (kt % NSTG) * STG_H;
        __nv_bfloat16* Bsb = Asb + A_H;

        if (kt + 2 < KT) {
            __nv_bfloat16* An = sm + ((kt + 2) % NSTG) * STG_H;
            load_tile(kt + 2, An, An + A_H);
        }
        asm volatile("cp.async.commit_group;\n" ::);
        asm volatile("cp.async.wait_group 2;\n" ::);
        __syncthreads();

        unsigned AsU = (unsigned)__cvta_generic_to_shared(Asb);
        unsigned BsU = (unsigned)__cvta_generic_to_shared(Bsb);

        #pragma unroll
        for (int ks = 0; ks < 2; ks++) {
            int k0h = ks * 16;
            unsigned a[4][4];
            #pragma unroll
            for (int i = 0; i < 4; i++) {
                int r = warpRow * 64 + i * 16 + (lane & 15);
                unsigned ad = AsU + (r * A_LDH + k0h + ((lane >> 4) << 3)) * 2;
                LDSM_X4(a[i][0], a[i][1], a[i][2], a[i][3], ad);
            }
            unsigned b[4][2];
            #pragma unroll
            for (int j2 = 0; j2 < 2; j2++) {
                int n0 = warpCol * 32 + j2 * 16;
                int r = k0h + (((lane >> 3) & 1) << 3) + (lane & 7);
                int c = n0 + ((lane >> 4) << 3);
                unsigned ad = BsU + (r * BNN_LDH + c) * 2;
                LDSM_X4T(b[2 * j2][0], b[2 * j2][1], b[2 * j2 + 1][0], b[2 * j2 + 1][1], ad);
            }
            #pragma unroll
            for (int i = 0; i < 4; i++)
                #pragma unroll
                for (int j = 0; j < 4; j++)
                    MMA_BF16(acc[i][j], a[i], b[j]);
        }
        __syncthreads();
    }

    #pragma unroll
    for (int i = 0; i < 4; i++) {
        int r = row0 + warpRow * 64 + i * 16 + grp;
        #pragma unroll
        for (int j = 0; j < 4; j++) {
            int c = col0 + warpCol * 32 + j * 8 + 2 * qid;
            float2 v0 = make_float2(acc[i][j][0], acc[i][j][1]);
            float2 v1 = make_float2(acc[i][j][2], acc[i][j][3]);
            if (BIAS) {
                float2 bb = *(const float2*)(bias + c);
                v0.x += bb.x; v0.y += bb.y;
                v1.x += bb.x; v1.y += bb.y;
            }
            if (RES) {
                float2 r0v = *(const float2*)(res + (long)r * N + c);
                float2 r1v = *(const float2*)(res + (long)(r + 8) * N + c);
                v0.x += r0v.x; v0.y += r0v.y;
                v1.x += r1v.x; v1.y += r1v.y;
            }
            if (OBF) {
                __nv_bfloat16* C = (__nv_bfloat16*)Cv;
                *(__nv_bfloat162*)(C + (long)r * N + c) =
                    __nv_bfloat162(__float2bfloat16(v0.x), __float2bfloat16(v0.y));
                *(__nv_bfloat162*)(C + (long)(r + 8) * N + c) =
                    __nv_bfloat162(__float2bfloat16(v1.x), __float2bfloat16(v1.y));
            } else {
                float* C = (float*)Cv;
                *(float2*)(C + (long)r * N + c)       = v0;
                *(float2*)(C + (long)(r + 8) * N + c) = v1;
            }
        }
    }
}

// ---------------------------------------------------------------------------
// Fused flash attention: per (head bh, q-tile of 128 rows), online softmax.
//   grid (8, 64), 256 threads (8 warps x 16 rows).
//   Faithful flat-head view: head bh = rows [bh*1024, bh*1024+1024) of the
//   flat [8192,128] Q/K/V buffers; mask batch = bh % 8.
// ---------------------------------------------------------------------------
#define FL_LDH     136
#define FL_TILE_H  (128 * FL_LDH)            // 17408 halves per tile
#define FL_SMEM    (5 * FL_TILE_H * 2)       // Q + 2*K + 2*V = 174080 B

__global__ void __launch_bounds__(256, 1)
flash_kernel(const __nv_bfloat16* __restrict__ Q,
             const __nv_bfloat16* __restrict__ K,
             const __nv_bfloat16* __restrict__ V,
             const float* __restrict__ nb,
             __nv_bfloat16* __restrict__ Octx) {
    extern __shared__ __nv_bfloat16 fsm[];
    __nv_bfloat16* Qs = fsm;                    // 1 tile
    __nv_bfloat16* Ks = fsm + FL_TILE_H;        // 2 stages
    __nv_bfloat16* Vs = fsm + 3 * FL_TILE_H;    // 2 stages

    int tid = threadIdx.x;
    int lane = tid & 31, wid = tid >> 5;
    int grp = lane >> 2, qid = lane & 3;
    int m0 = wid * 16;

    int bh = blockIdx.y;
    int q0 = blockIdx.x * 128;
    const __nv_bfloat16* Qg = Q + (long)bh * 131072 + (long)q0 * 128;
    const __nv_bfloat16* Kg = K + (long)bh * 131072;
    const __nv_bfloat16* Vg = V + (long)bh * 131072;
    const float* nbr = nb + ((bh & 7) << 10);
    __nv_bfloat16* Cg = Octx + (long)bh * 131072 + (long)q0 * 128;

    auto loadKV = [&](int kt, int stg) {
        const __nv_bfloat16* Kt = Kg + (long)kt * 16384;
        const __nv_bfloat16* Vt = Vg + (long)kt * 16384;
        __nv_bfloat16* Kd = Ks + stg * FL_TILE_H;
        __nv_bfloat16* Vd = Vs + stg * FL_TILE_H;
        #pragma unroll
        for (int p = 0; p < 8; p++) {
            int idx = p * 256 + tid;
            int r = idx >> 4, cc = (idx & 15) << 3;
            cpa16(Kd + r * FL_LDH + cc, Kt + r * 128 + cc);
        }
        #pragma unroll
        for (int p = 0; p < 8; p++) {
            int idx = p * 256 + tid;
            int r = idx >> 4, cc = (idx & 15) << 3;
            cpa16(Vd + r * FL_LDH + cc, Vt + r * 128 + cc);
        }
    };

    // prologue: Q + K0/V0
    #pragma unroll
    for (int p = 0; p < 8; p++) {
        int idx = p * 256 + tid;
        int r = idx >> 4, cc = (idx & 15) << 3;
        cpa16(Qs + r * FL_LDH + cc, Qg + r * 128 + cc);
    }
    loadKV(0, 0);
    asm volatile("cp.async.commit_group;\n" ::);

    float o[16][4];
    #pragma unroll
    for (int j = 0; j < 16; j++)
        #pragma unroll
        for (int t = 0; t < 4; t++) o[j][t] = 0.0f;
    float mrow0 = -1e30f, mrow1 = -1e30f;
    float lrow0 = 0.0f,  lrow1 = 0.0f;

    unsigned QsU = (unsigned)__cvta_generic_to_shared(Qs);

    for (int kt = 0; kt < 8; kt++) {
        int stg = kt & 1;
        if (kt < 7) loadKV(kt + 1, stg ^ 1);
        asm volatile("cp.async.commit_group;\n" ::);
        asm volatile("cp.async.wait_group 1;\n" ::);
        __syncthreads();

        unsigned KsU = (unsigned)__cvta_generic_to_shared(Ks + stg * FL_TILE_H);
        unsigned VsU = (unsigned)__cvta_generic_to_shared(Vs + stg * FL_TILE_H);

        // ---- S = Q K^T  (warp: 16 rows x 128 keys) ----
        float s[16][4];
        #pragma unroll
        for (int j = 0; j < 16; j++)
            #pragma unroll
            for (int t = 0; t < 4; t++) s[j][t] = 0.0f;

        #pragma unroll
        for (int kf = 0; kf < 8; kf++) {
            unsigned aq[4];
            {
                int r = m0 + (lane & 15);
                int c = kf * 16 + ((lane >> 4) << 3);
                LDSM_X4(aq[0], aq[1], aq[2], aq[3], QsU + (r * FL_LDH + c) * 2);
            }
            #pragma unroll
            for (int j2 = 0; j2 < 8; j2++) {
                unsigned bq[4];
                int rn = j2 * 16 + ((lane >> 4) << 3) + (lane & 7);
                int ck = kf * 16 + (((lane >> 3) & 1) << 3);
                LDSM_X4(bq[0], bq[1], bq[2], bq[3], KsU + (rn * FL_LDH + ck) * 2);
                MMA_BF16(s[2 * j2],     aq, bq);
                MMA_BF16(s[2 * j2 + 1], aq, (bq + 2));
            }
        }

        // ---- scale + mask + online softmax ----
        int kb = kt << 7;
        float mx0 = mrow0, mx1 = mrow1;
        #pragma unroll
        for (int j = 0; j < 16; j++) {
            float2 msk = *(const float2*)(nbr + kb + j * 8 + 2 * qid);
            s[j][0] = fmaf(s[j][0], SCALE_F, msk.x);
            s[j][1] = fmaf(s[j][1], SCALE_F, msk.y);
            s[j][2] = fmaf(s[j][2], SCALE_F, msk.x);
            s[j][3] = fmaf(s[j][3], SCALE_F, msk.y);
            mx0 = fmaxf(mx0, fmaxf(s[j][0], s[j][1]));
            mx1 = fmaxf(mx1, fmaxf(s[j][2], s[j][3]));
        }
        mx0 = fmaxf(mx0, __shfl_xor_sync(0xffffffffu, mx0, 1));
        mx0 = fmaxf(mx0, __shfl_xor_sync(0xffffffffu, mx0, 2));
        mx1 = fmaxf(mx1, __shfl_xor_sync(0xffffffffu, mx1, 1));
        mx1 = fmaxf(mx1, __shfl_xor_sync(0xffffffffu, mx1, 2));

        float al0 = exp2f((mrow0 - mx0) * LOG2E_F);
        float al1 = exp2f((mrow1 - mx1) * LOG2E_F);
        mrow0 = mx0; mrow1 = mx1;

        float r0 = 0.0f, r1 = 0.0f;
        #pragma unroll
        for (int j = 0; j < 16; j++) {
            s[j][0] = exp2f((s[j][0] - mx0) * LOG2E_F);
            s[j][1] = exp2f((s[j][1] - mx0) * LOG2E_F);
            s[j][2] = exp2f((s[j][2] - mx1) * LOG2E_F);
            s[j][3] = exp2f((s[j][3] - mx1) * LOG2E_F);
            r0 += s[j][0] + s[j][1];
            r1 += s[j][2] + s[j][3];
            o[j][0] *= al0; o[j][1] *= al0;
            o[j][2] *= al1; o[j][3] *= al1;
        }
        lrow0 = lrow0 * al0 + r0;
        lrow1 = lrow1 * al1 + r1;

        // ---- O += P V  (S accum fragments == A fragments, no shuffle) ----
        #pragma unroll
        for (int t = 0; t < 8; t++) {
            unsigned ap[4];
            __nv_bfloat162 p0 = __floats2bfloat162_rn(s[2 * t][0],     s[2 * t][1]);
            __nv_bfloat162 p1 = __floats2bfloat162_rn(s[2 * t][2],     s[2 * t][3]);
            __nv_bfloat162 p2 = __floats2bfloat162_rn(s[2 * t + 1][0], s[2 * t + 1][1]);
            __nv_bfloat162 p3 = __floats2bfloat162_rn(s[2 * t + 1][2], s[2 * t + 1][3]);
            ap[0] = *(unsigned*)&p0;
            ap[1] = *(unsigned*)&p1;
            ap[2] = *(unsigned*)&p2;
            ap[3] = *(unsigned*)&p3;
            #pragma unroll
            for (int j2 = 0; j2 < 8; j2++) {
                unsigned bv[4];
                int rk = t * 16 + (((lane >> 3) & 1) << 3) + (lane & 7);
                int cn = j2 * 16 + ((lane >> 4) << 3);
                LDSM_X4T(bv[0], bv[1], bv[2], bv[3], VsU + (rk * FL_LDH + cn) * 2);
                MMA_BF16(o[2 * j2],     ap, bv);
                MMA_BF16(o[2 * j2 + 1], ap, (bv + 2));
            }
        }
        __syncthreads();
    }

    // ---- epilogue: normalize, store bf16 ctx ----
    lrow0 += __shfl_xor_sync(0xffffffffu, lrow0, 1);
    lrow0 += __shfl_xor_sync(0xffffffffu, lrow0, 2);
    lrow1 += __shfl_xor_sync(0xffffffffu, lrow1, 1);
    lrow1 += __shfl_xor_sync(0xffffffffu, lrow1, 2);
    float inv0 = 1.0f / lrow0;
    float inv1 = 1.0f / lrow1;

    int r0i = m0 + grp, r1i = m0 + grp + 8;
    #pragma unroll
    for (int j = 0; j < 16; j++) {
        int c = j * 8 + 2 * qid;
        *(__nv_bfloat162*)(Cg + (long)r0i * 128 + c) =
            __floats2bfloat162_rn(o[j][0] * inv0, o[j][1] * inv0);
        *(__nv_bfloat162*)(Cg + (long)r1i * 128 + c) =
            __floats2bfloat162_rn(o[j][2] * inv1, o[j][3] * inv1);
    }
}

// ---------------------------------------------------------------------------
// Pooling + LayerNorm
// ---------------------------------------------------------------------------
__global__ void pool_kernel(const float* __restrict__ r, float* __restrict__ agg) {
    int b = blockIdx.x;
    int d = blockIdx.y * 128 + threadIdx.x;
    const float* base = r + ((long)b << 20) + d;
    float mx = -INFINITY, sm = 0.0f;
    #pragma unroll 4
    for (int l = 0; l < N_L; l++) {
        float v = base[(long)l << 10];
        mx = fmaxf(mx, v);
        sm += v;
    }
    agg[b * 2048 + d]        = mx;
    agg[b * 2048 + 1024 + d] = sm * (1.0f / 1024.0f);
}

__global__ void __launch_bounds__(256)
ln_kernel(const float* __restrict__ agg, const float* __restrict__ gamma,
          const float* __restrict__ beta, float* __restrict__ out) {
    int b = blockIdx.x, tid = threadIdx.x;
    const float* a = agg + b * 2048;
    float s = 0.0f;
    #pragma unroll
    for (int i = 0; i < 8; i++) s += a[tid + i * 256];
    s = blockSum(s);
    float mu = s * (1.0f / 2048.0f);
    float vs = 0.0f;
    #pragma unroll
    for (int i = 0; i < 8; i++) {
        float d = a[tid + i * 256] - mu;
        vs += d * d;
    }
    vs = blockSum(vs);
    float inv = rsqrtf(vs * (1.0f / 2048.0f) + EPS_F);
    #pragma unroll
    for (int i = 0; i < 8; i++) {
        int k = tid + i * 256;
        out[b * 2048 + k] = (a[k] - mu) * inv * gamma[k] + beta[k];
    }
}

// ---------------------------------------------------------------------------
// Launch
// ---------------------------------------------------------------------------
extern "C" void kernel_launch(void* const* d_in, const int* in_sizes, int n_in,
                              void* d_out, int out_size) {
    const int*   tokens = (const int*)  d_in[0];
    const float* emb    = (const float*)d_in[1];
    const float* Wq     = (const float*)d_in[2];
    const float* bq     = (const float*)d_in[3];
    const float* Wk     = (const float*)d_in[4];
    const float* bk     = (const float*)d_in[5];
    const float* Wv     = (const float*)d_in[6];
    const float* bv     = (const float*)d_in[7];
    const float* Wo     = (const float*)d_in[8];
    const float* bo     = (const float*)d_in[9];
    const float* gamma  = (const float*)d_in[10];
    const float* beta   = (const float*)d_in[11];
    float* out = (float*)d_out;

    float *x, *r, *nb, *agg;
    __nv_bfloat16 *xb, *qb, *kb, *vb, *cb, *wq, *wk, *wv, *wo;
    cudaGetSymbolAddress((void**)&x,   g_x);
    cudaGetSymbolAddress((void**)&r,   g_r);
    cudaGetSymbolAddress((void**)&nb,  g_nb);
    cudaGetSymbolAddress((void**)&agg, g_agg);
    cudaGetSymbolAddress((void**)&xb,  g_xb);
    cudaGetSymbolAddress((void**)&qb,  g_qb);
    cudaGetSymbolAddress((void**)&kb,  g_kb);
    cudaGetSymbolAddress((void**)&vb,  g_vb);
    cudaGetSymbolAddress((void**)&cb,  g_cb);
    cudaGetSymbolAddress((void**)&wq,  g_wq);
    cudaGetSymbolAddress((void**)&wk,  g_wk);
    cudaGetSymbolAddress((void**)&wv,  g_wv);
    cudaGetSymbolAddress((void**)&wo,  g_wo);

    cudaFuncSetAttribute(gemm_bf<true,  false, true>,
                         cudaFuncAttributeMaxDynamicSharedMemorySize, SMEM_BYTES);
    cudaFuncSetAttribute(gemm_bf<true,  true,  false>,
                         cudaFuncAttributeMaxDynamicSharedMemorySize, SMEM_BYTES);
    cudaFuncSetAttribute(flash_kernel,
                         cudaFuncAttributeMaxDynamicSharedMemorySize, FL_SMEM);

    // 1. embed (f32 + bf16), mask, weight conversion
    embed_kernel<<<N_B * N_L, 256>>>(tokens, emb, x, xb);
    mask_kernel<<<8, 1024>>>(tokens, nb);
    conv_kernel<<<2048, 256>>>(Wq, wq);
    conv_kernel<<<2048, 256>>>(Wk, wk);
    conv_kernel<<<2048, 256>>>(Wv, wv);
    conv_kernel<<<2048, 256>>>(Wo, wo);

    // 2. Q/K/V projections -> bf16
    dim3 gProj(8, 64, 1);
    gemm_bf<true, false, true><<<gProj, 256, SMEM_BYTES>>>(
        xb, wq, bq, nullptr, qb, 8192, 1024, 1024);
    gemm_bf<true, false, true><<<gProj, 256, SMEM_BYTES>>>(
        xb, wk, bk, nullptr, kb, 8192, 1024, 1024);
    gemm_bf<true, false, true><<<gProj, 256, SMEM_BYTES>>>(
        xb, wv, bv, nullptr, vb, 8192, 1024, 1024);

    // 3-5. fused attention (QK^T + softmax + PV) -> bf16 ctx
    flash_kernel<<<dim3(8, 64), 256, FL_SMEM>>>(qb, kb, vb, nb, cb);

    // 6. r = x + ctx @ Wo + bo -> f32
    gemm_bf<true, true, false><<<gProj, 256, SMEM_BYTES>>>(
        cb, wo, bo, x, r, 8192, 1024, 1024);

    // 7. pool + layernorm
    pool_kernel<<<dim3(8, 8), 128>>>(r, agg);
    ln_kernel<<<8, 256>>>(agg, gamma, beta, out);
}

// round 11
// speedup vs baseline: 6.1652x; 1.1334x over previous
#include <cuda_runtime.h>
#include <cuda_bf16.h>
#include <math.h>

// Shapes (fixed): B=8, L=1024, D=1024, H=8, DH=128, BH=64
#define N_B    8
#define N_L    1024
#define N_D    1024
#define SCALE_F 0.25f
#define EPS_F   1e-5f
#define LOG2E_F 1.4426950408889634f

// ---------------------------------------------------------------------------
// Scratch
// ---------------------------------------------------------------------------
__device__ float g_x[8u * 1024u * 1024u];     // embedded input (f32, residual)
__device__ float g_r[8u * 1024u * 1024u];     // r = x + out (f32)
__device__ float g_nb[8 * 1024];              // -inf mask bias
__device__ float g_pmx[8 * 8 * 1024];         // pool partial max [b][slice][d]
__device__ float g_psm[8 * 8 * 1024];         // pool partial sum

__device__ __nv_bfloat16 g_xb[8u * 1024u * 1024u];   // x bf16
__device__ __nv_bfloat16 g_qb[8u * 1024u * 1024u];   // Q bf16
__device__ __nv_bfloat16 g_kb[8u * 1024u * 1024u];   // K bf16
__device__ __nv_bfloat16 g_vb[8u * 1024u * 1024u];   // V bf16
__device__ __nv_bfloat16 g_cb[8u * 1024u * 1024u];   // ctx bf16
__device__ __nv_bfloat16 g_wq[1024 * 1024];
__device__ __nv_bfloat16 g_wk[1024 * 1024];
__device__ __nv_bfloat16 g_wv[1024 * 1024];
__device__ __nv_bfloat16 g_wo[1024 * 1024];

// ---------------------------------------------------------------------------
// Helpers
// ---------------------------------------------------------------------------
__device__ __forceinline__ void cpa16(void* dst_smem, const void* src_gmem) {
    unsigned d = (unsigned)__cvta_generic_to_shared(dst_smem);
    asm volatile("cp.async.cg.shared.global [%0], [%1], 16;\n"
                 :: "r"(d), "l"(src_gmem));
}

__device__ __forceinline__ float blockSum(float v) {
    __shared__ float sh[32];
    int lane = threadIdx.x & 31, wid = threadIdx.x >> 5;
    #pragma unroll
    for (int o = 16; o > 0; o >>= 1) v += __shfl_xor_sync(0xffffffffu, v, o);
    if (lane == 0) sh[wid] = v;
    __syncthreads();
    int nw = blockDim.x >> 5;
    float r = (threadIdx.x < (unsigned)nw) ? sh[threadIdx.x] : 0.0f;
    if (wid == 0) {
        #pragma unroll
        for (int o = 16; o > 0; o >>= 1) r += __shfl_xor_sync(0xffffffffu, r, o);
        if (lane == 0) sh[0] = r;
    }
    __syncthreads();
    float out = sh[0];
    __syncthreads();
    return out;
}

// ---------------------------------------------------------------------------
// Embedding (f32 + bf16) + mask + fused 4-weight convert
// ---------------------------------------------------------------------------
__global__ void embed_kernel(const int* __restrict__ tokens,
                             const float* __restrict__ emb,
                             float* __restrict__ x,
                             __nv_bfloat16* __restrict__ xb) {
    int row = blockIdx.x;
    int tok = tokens[row];
    float4 v = ((const float4*)(emb + (long)tok * N_D))[threadIdx.x];
    ((float4*)(x + (long)row * N_D))[threadIdx.x] = v;
    __nv_bfloat162* db = (__nv_bfloat162*)(xb + (long)row * N_D);
    db[2 * threadIdx.x]     = __nv_bfloat162(__float2bfloat16(v.x), __float2bfloat16(v.y));
    db[2 * threadIdx.x + 1] = __nv_bfloat162(__float2bfloat16(v.z), __float2bfloat16(v.w));
}

__global__ void mask_kernel(const int* __restrict__ tokens, float* __restrict__ nb) {
    int i = blockIdx.x * blockDim.x + threadIdx.x;
    nb[i] = (tokens[i] == 0) ? -INFINITY : 0.0f;
}

__global__ void conv4_kernel(const float* __restrict__ s0, const float* __restrict__ s1,
                             const float* __restrict__ s2, const float* __restrict__ s3,
                             __nv_bfloat16* __restrict__ d0, __nv_bfloat16* __restrict__ d1,
                             __nv_bfloat16* __restrict__ d2, __nv_bfloat16* __restrict__ d3) {
    int w = blockIdx.x >> 11;
    const float* src = (w == 0) ? s0 : (w == 1) ? s1 : (w == 2) ? s2 : s3;
    __nv_bfloat16* dst = (w == 0) ? d0 : (w == 1) ? d1 : (w == 2) ? d2 : d3;
    int i = (blockIdx.x & 2047) * blockDim.x + threadIdx.x;
    float2 v = ((const float2*)src)[i];
    ((__nv_bfloat162*)dst)[i] = __nv_bfloat162(__float2bfloat16(v.x), __float2bfloat16(v.y));
}

// ---------------------------------------------------------------------------
// bf16 MMA + ldmatrix
// ---------------------------------------------------------------------------
#define MMA_BF16(d, a, b)                                                     \
    asm volatile(                                                             \
        "mma.sync.aligned.m16n8k16.row.col.f32.bf16.bf16.f32 "                \
        "{%0,%1,%2,%3},{%4,%5,%6,%7},{%8,%9},{%0,%1,%2,%3};"                  \
        : "+f"((d)[0]), "+f"((d)[1]), "+f"((d)[2]), "+f"((d)[3])              \
        : "r"((a)[0]), "r"((a)[1]), "r"((a)[2]), "r"((a)[3]),                 \
          "r"((b)[0]), "r"((b)[1]))

#define LDSM_X4(r0, r1, r2, r3, addr)                                         \
    asm volatile("ldmatrix.sync.aligned.m8n8.x4.shared.b16 {%0,%1,%2,%3}, [%4];" \
                 : "=r"(r0), "=r"(r1), "=r"(r2), "=r"(r3) : "r"(addr))

#define LDSM_X4T(r0, r1, r2, r3, addr)                                        \
    asm volatile("ldmatrix.sync.aligned.m8n8.x4.trans.shared.b16 {%0,%1,%2,%3}, [%4];" \
                 : "=r"(r0), "=r"(r1), "=r"(r2), "=r"(r3) : "r"(addr))

// ---------------------------------------------------------------------------
// GEMM SMEM geometry
// ---------------------------------------------------------------------------
#define A_LDH   40
#define BNN_LDH 136
#define A_H     (128 * A_LDH)
#define B_H     5120
#define STG_H   (A_H + B_H)
#define NSTG    3
#define SMEM_BYTES (NSTG * STG_H * 2)

// ---------------------------------------------------------------------------
// bf16 NN tensor GEMM (projections + Wo): 128x128x32 tile, 3-stage cp.async.
// ---------------------------------------------------------------------------
template <bool BIAS, bool RES, bool OBF>
__global__ void __launch_bounds__(256)
gemm_bf(const __nv_bfloat16* __restrict__ A, const __nv_bfloat16* __restrict__ B,
        const float* __restrict__ bias, const float* __restrict__ res,
        void* __restrict__ Cv, int M, int N, int K) {
    extern __shared__ __nv_bfloat16 sm[];

    int tid = threadIdx.x;
    int lane = tid & 31, wid = tid >> 5;
    int warpRow = wid >> 2, warpCol = wid & 3;
    int grp = lane >> 2, qid = lane & 3;

    int row0 = blockIdx.y * 128;
    int col0 = blockIdx.x * 128;
    int KT = K >> 5;

    auto load_tile = [&](int kt, __nv_bfloat16* Asb, __nv_bfloat16* Bsb) {
        int k0 = kt << 5;
        #pragma unroll
        for (int p = 0; p < 2; p++) {
            int idx = p * 256 + tid;
            int r = idx >> 2, cc = (idx & 3) << 3;
            cpa16(Asb + r * A_LDH + cc, A + (long)(row0 + r) * K + k0 + cc);
        }
        #pragma unroll
        for (int p = 0; p < 2; p++) {
            int idx = p * 256 + tid;
            int r = idx >> 4, cc = (idx & 15) << 3;
            cpa16(Bsb + r * BNN_LDH + cc, B + (long)(k0 + r) * N + col0 + cc);
        }
    };

    float acc[4][4][4];
    #pragma unroll
    for (int i = 0; i < 4; i++)
        #pragma unroll
        for (int j = 0; j < 4; j++)
            #pragma unroll
            for (int t = 0; t < 4; t++) acc[i][j][t] = 0.0f;

    load_tile(0, sm, sm + A_H);
    asm volatile("cp.async.commit_group;\n" ::);
    if (KT > 1) load_tile(1, sm + STG_H, sm + STG_H + A_H);
    asm volatile("cp.async.commit_group;\n" ::);

    for (int kt = 0; kt < KT; kt++) {
        __nv_bfloat16* Asb = sm + (kt % NSTG) * STG_H;
        __nv_bfloat16* Bsb = Asb + A_H;

        if (kt + 2 < KT) {
            __nv_bfloat16* An = sm + ((kt + 2) % NSTG) * STG_H;
            load_tile(kt + 2, An, An + A_H);
        }
        asm volatile("cp.async.commit_group;\n" ::);
        asm volatile("cp.async.wait_group 2;\n" ::);
        __syncthreads();

        unsigned AsU = (unsigned)__cvta_generic_to_shared(Asb);
        unsigned BsU = (unsigned)__cvta_generic_to_shared(Bsb);

        #pragma unroll
        for (int ks = 0; ks < 2; ks++) {
            int k0h = ks * 16;
            unsigned a[4][4];
            #pragma unroll
            for (int i = 0; i < 4; i++) {
                int r = warpRow * 64 + i * 16 + (lane & 15);
                unsigned ad = AsU + (r * A_LDH + k0h + ((lane >> 4) << 3)) * 2;
                LDSM_X4(a[i][0], a[i][1], a[i][2], a[i][3], ad);
            }
            unsigned b[4][2];
            #pragma unroll
            for (int j2 = 0; j2 < 2; j2++) {
                int n0 = warpCol * 32 + j2 * 16;
                int r = k0h + (((lane >> 3) & 1) << 3) + (lane & 7);
                int c = n0 + ((lane >> 4) << 3);
                unsigned ad = BsU + (r * BNN_LDH + c) * 2;
                LDSM_X4T(b[2 * j2][0], b[2 * j2][1], b[2 * j2 + 1][0], b[2 * j2 + 1][1], ad);
            }
            #pragma unroll
            for (int i = 0; i < 4; i++)
                #pragma unroll
                for (int j = 0; j < 4; j++)
                    MMA_BF16(acc[i][j], a[i], b[j]);
        }
        __syncthreads();
    }

    #pragma unroll
    for (int i = 0; i < 4; i++) {
        int r = row0 + warpRow * 64 + i * 16 + grp;
        #pragma unroll
        for (int j = 0; j < 4; j++) {
            int c = col0 + warpCol * 32 + j * 8 + 2 * qid;
            float2 v0 = make_float2(acc[i][j][0], acc[i][j][1]);
            float2 v1 = make_float2(acc[i][j][2], acc[i][j][3]);
            if (BIAS) {
                float2 bb = *(const float2*)(bias + c);
                v0.x += bb.x; v0.y += bb.y;
                v1.x += bb.x; v1.y += bb.y;
            }
            if (RES) {
                float2 r0v = *(const float2*)(res + (long)r * N + c);
                float2 r1v = *(const float2*)(res + (long)(r + 8) * N + c);
                v0.x += r0v.x; v0.y += r0v.y;
                v1.x += r1v.x; v1.y += r1v.y;
            }
            if (OBF) {
                __nv_bfloat16* C = (__nv_bfloat16*)Cv;
                *(__nv_bfloat162*)(C + (long)r * N + c) =
                    __nv_bfloat162(__float2bfloat16(v0.x), __float2bfloat16(v0.y));
                *(__nv_bfloat162*)(C + (long)(r + 8) * N + c) =
                    __nv_bfloat162(__float2bfloat16(v1.x), __float2bfloat16(v1.y));
            } else {
                float* C = (float*)Cv;
                *(float2*)(C + (long)r * N + c)       = v0;
                *(float2*)(C + (long)(r + 8) * N + c) = v1;
            }
        }
    }
}

// ---------------------------------------------------------------------------
// Fused flash attention, 64-row KV tiles, 2 CTAs/SM.
//   grid (8, 64), 256 threads (8 warps x 16 q-rows).
//   Flat-head view: head bh = rows [bh*1024, +1024) of [8192,128] buffers;
//   mask batch = bh % 8 (faithful to reference).
// ---------------------------------------------------------------------------
#define FL_LDH     136
#define FL_Q_H     (128 * FL_LDH)            // 17408 halves
#define FL_KV_H    (64 * FL_LDH)             // 8704 halves
#define FL_SMEM    ((FL_Q_H + 4 * FL_KV_H) * 2)   // 104448 B

__global__ void __launch_bounds__(256, 2)
flash_kernel(const __nv_bfloat16* __restrict__ Q,
             const __nv_bfloat16* __restrict__ K,
             const __nv_bfloat16* __restrict__ V,
             const float* __restrict__ nb,
             __nv_bfloat16* __restrict__ Octx) {
    extern __shared__ __nv_bfloat16 fsm[];
    __nv_bfloat16* Qs = fsm;                        // 128x128
    __nv_bfloat16* Ks = fsm + FL_Q_H;               // 2 stages x 64x128
    __nv_bfloat16* Vs = fsm + FL_Q_H + 2 * FL_KV_H; // 2 stages x 64x128

    int tid = threadIdx.x;
    int lane = tid & 31, wid = tid >> 5;
    int grp = lane >> 2, qid = lane & 3;
    int m0 = wid * 16;

    int bh = blockIdx.y;
    int q0 = blockIdx.x * 128;
    const __nv_bfloat16* Qg = Q + (long)bh * 131072 + (long)q0 * 128;
    const __nv_bfloat16* Kg = K + (long)bh * 131072;
    const __nv_bfloat16* Vg = V + (long)bh * 131072;
    const float* nbr = nb + ((bh & 7) << 10);
    __nv_bfloat16* Cg = Octx + (long)bh * 131072 + (long)q0 * 128;

    auto loadKV = [&](int kt, int stg) {
        const __nv_bfloat16* Kt = Kg + (long)kt * 8192;
        const __nv_bfloat16* Vt = Vg + (long)kt * 8192;
        __nv_bfloat16* Kd = Ks + stg * FL_KV_H;
        __nv_bfloat16* Vd = Vs + stg * FL_KV_H;
        #pragma unroll
        for (int p = 0; p < 4; p++) {
            int idx = p * 256 + tid;
            int r = idx >> 4, cc = (idx & 15) << 3;
            cpa16(Kd + r * FL_LDH + cc, Kt + r * 128 + cc);
        }
        #pragma unroll
        for (int p = 0; p < 4; p++) {
            int idx = p * 256 + tid;
            int r = idx >> 4, cc = (idx & 15) << 3;
            cpa16(Vd + r * FL_LDH + cc, Vt + r * 128 + cc);
        }
    };

    // prologue: Q + K0/V0
    #pragma unroll
    for (int p = 0; p < 8; p++) {
        int idx = p * 256 + tid;
        int r = idx >> 4, cc = (idx & 15) << 3;
        cpa16(Qs + r * FL_LDH + cc, Qg + r * 128 + cc);
    }
    loadKV(0, 0);
    asm volatile("cp.async.commit_group;\n" ::);

    float o[16][4];
    #pragma unroll
    for (int j = 0; j < 16; j++)
        #pragma unroll
        for (int t = 0; t < 4; t++) o[j][t] = 0.0f;
    float mrow0 = -1e30f, mrow1 = -1e30f;
    float lrow0 = 0.0f,  lrow1 = 0.0f;

    unsigned QsU = (unsigned)__cvta_generic_to_shared(Qs);

    #pragma unroll 1
    for (int kt = 0; kt < 16; kt++) {
        int stg = kt & 1;
        if (kt < 15) loadKV(kt + 1, stg ^ 1);
        asm volatile("cp.async.commit_group;\n" ::);
        asm volatile("cp.async.wait_group 1;\n" ::);
        __syncthreads();

        unsigned KsU = (unsigned)__cvta_generic_to_shared(Ks + stg * FL_KV_H);
        unsigned VsU = (unsigned)__cvta_generic_to_shared(Vs + stg * FL_KV_H);

        // ---- S = Q K^T  (warp: 16 rows x 64 keys) ----
        float s[8][4];
        #pragma unroll
        for (int j = 0; j < 8; j++)
            #pragma unroll
            for (int t = 0; t < 4; t++) s[j][t] = 0.0f;

        #pragma unroll
        for (int kf = 0; kf < 8; kf++) {
            unsigned aq[4];
            {
                int r = m0 + (lane & 15);
                int c = kf * 16 + ((lane >> 4) << 3);
                LDSM_X4(aq[0], aq[1], aq[2], aq[3], QsU + (r * FL_LDH + c) * 2);
            }
            #pragma unroll
            for (int j2 = 0; j2 < 4; j2++) {
                unsigned bq[4];
                int rn = j2 * 16 + ((lane >> 4) << 3) + (lane & 7);
                int ck = kf * 16 + (((lane >> 3) & 1) << 3);
                LDSM_X4(bq[0], bq[1], bq[2], bq[3], KsU + (rn * FL_LDH + ck) * 2);
                MMA_BF16(s[2 * j2],     aq, bq);
                MMA_BF16(s[2 * j2 + 1], aq, (bq + 2));
            }
        }

        // ---- scale + mask + online softmax ----
        int kb = kt << 6;
        float mx0 = mrow0, mx1 = mrow1;
        #pragma unroll
        for (int j = 0; j < 8; j++) {
            float2 msk = *(const float2*)(nbr + kb + j * 8 + 2 * qid);
            s[j][0] = fmaf(s[j][0], SCALE_F, msk.x);
            s[j][1] = fmaf(s[j][1], SCALE_F, msk.y);
            s[j][2] = fmaf(s[j][2], SCALE_F, msk.x);
            s[j][3] = fmaf(s[j][3], SCALE_F, msk.y);
            mx0 = fmaxf(mx0, fmaxf(s[j][0], s[j][1]));
            mx1 = fmaxf(mx1, fmaxf(s[j][2], s[j][3]));
        }
        mx0 = fmaxf(mx0, __shfl_xor_sync(0xffffffffu, mx0, 1));
        mx0 = fmaxf(mx0, __shfl_xor_sync(0xffffffffu, mx0, 2));
        mx1 = fmaxf(mx1, __shfl_xor_sync(0xffffffffu, mx1, 1));
        mx1 = fmaxf(mx1, __shfl_xor_sync(0xffffffffu, mx1, 2));

        float al0 = exp2f((mrow0 - mx0) * LOG2E_F);
        float al1 = exp2f((mrow1 - mx1) * LOG2E_F);
        mrow0 = mx0; mrow1 = mx1;

        float r0 = 0.0f, r1 = 0.0f;
        #pragma unroll
        for (int j = 0; j < 8; j++) {
            s[j][0] = exp2f((s[j][0] - mx0) * LOG2E_F);
            s[j][1] = exp2f((s[j][1] - mx0) * LOG2E_F);
            s[j][2] = exp2f((s[j][2] - mx1) * LOG2E_F);
            s[j][3] = exp2f((s[j][3] - mx1) * LOG2E_F);
            r0 += s[j][0] + s[j][1];
            r1 += s[j][2] + s[j][3];
        }
        #pragma unroll
        for (int j = 0; j < 16; j++) {
            o[j][0] *= al0; o[j][1] *= al0;
            o[j][2] *= al1; o[j][3] *= al1;
        }
        lrow0 = lrow0 * al0 + r0;
        lrow1 = lrow1 * al1 + r1;

        // ---- O += P V  (S accum fragments == A fragments) ----
        #pragma unroll
        for (int t = 0; t < 4; t++) {
            unsigned ap[4];
            __nv_bfloat162 p0 = __floats2bfloat162_rn(s[2 * t][0],     s[2 * t][1]);
            __nv_bfloat162 p1 = __floats2bfloat162_rn(s[2 * t][2],     s[2 * t][3]);
            __nv_bfloat162 p2 = __floats2bfloat162_rn(s[2 * t + 1][0], s[2 * t + 1][1]);
            __nv_bfloat162 p3 = __floats2bfloat162_rn(s[2 * t + 1][2], s[2 * t + 1][3]);
            ap[0] = *(unsigned*)&p0;
            ap[1] = *(unsigned*)&p1;
            ap[2] = *(unsigned*)&p2;
            ap[3] = *(unsigned*)&p3;
            #pragma unroll
            for (int j2 = 0; j2 < 8; j2++) {
                unsigned bv[4];
                int rk = t * 16 + (((lane >> 3) & 1) << 3) + (lane & 7);
                int cn = j2 * 16 + ((lane >> 4) << 3);
                LDSM_X4T(bv[0], bv[1], bv[2], bv[3], VsU + (rk * FL_LDH + cn) * 2);
                MMA_BF16(o[2 * j2],     ap, bv);
                MMA_BF16(o[2 * j2 + 1], ap, (bv + 2));
            }
        }
        __syncthreads();
    }

    // ---- epilogue: normalize, store bf16 ctx ----
    lrow0 += __shfl_xor_sync(0xffffffffu, lrow0, 1);
    lrow0 += __shfl_xor_sync(0xffffffffu, lrow0, 2);
    lrow1 += __shfl_xor_sync(0xffffffffu, lrow1, 1);
    lrow1 += __shfl_xor_sync(0xffffffffu, lrow1, 2);
    float inv0 = 1.0f / lrow0;
    float inv1 = 1.0f / lrow1;

    int r0i = m0 + grp, r1i = m0 + grp + 8;
    #pragma unroll
    for (int j = 0; j < 16; j++) {
        int c = j * 8 + 2 * qid;
        *(__nv_bfloat162*)(Cg + (long)r0i * 128 + c) =
            __floats2bfloat162_rn(o[j][0] * inv0, o[j][1] * inv0);
        *(__nv_bfloat162*)(Cg + (long)r1i * 128 + c) =
            __floats2bfloat162_rn(o[j][2] * inv1, o[j][3] * inv1);
    }
}

// ---------------------------------------------------------------------------
// Pooling (sliced over L) + fused reduce/LayerNorm
// ---------------------------------------------------------------------------
__global__ void pool1_kernel(const float* __restrict__ r,
                             float* __restrict__ pmx, float* __restrict__ psm) {
    int b = blockIdx.x, dc = blockIdx.y, sl = blockIdx.z;
    int d = dc * 128 + threadIdx.x;
    const float* base = r + ((long)b << 20) + ((long)sl << 17) + d;
    float mx = -INFINITY, sm = 0.0f;
    #pragma unroll 4
    for (int l = 0; l < 128; l++) {
        float v = base[(long)l << 10];
        mx = fmaxf(mx, v);
        sm += v;
    }
    pmx[(((b << 3) + sl) << 10) + d] = mx;
    psm[(((b << 3) + sl) << 10) + d] = sm;
}

__global__ void __launch_bounds__(256)
ln_kernel(const float* __restrict__ pmx, const float* __restrict__ psm,
          const float* __restrict__ gamma, const float* __restrict__ beta,
          float* __restrict__ out) {
    int b = blockIdx.x, tid = threadIdx.x;
    float av[8];
    #pragma unroll
    for (int i = 0; i < 8; i++) {
        int k = tid + i * 256;
        if (k < 1024) {
            float mx = -INFINITY;
            #pragma unroll
            for (int sl = 0; sl < 8; sl++)
                mx = fmaxf(mx, pmx[(((b << 3) + sl) << 10) + k]);
            av[i] = mx;
        } else {
            int d = k - 1024;
            float sm = 0.0f;
            #pragma unroll
            for (int sl = 0; sl < 8; sl++)
                sm += psm[(((b << 3) + sl) << 10) + d];
            av[i] = sm * (1.0f / 1024.0f);
        }
    }
    float s = 0.0f;
    #pragma unroll
    for (int i = 0; i < 8; i++) s += av[i];
    s = blockSum(s);
    float mu = s * (1.0f / 2048.0f);
    float vs = 0.0f;
    #pragma unroll
    for (int i = 0; i < 8; i++) {
        float d = av[i] - mu;
        vs += d * d;
    }
    vs = blockSum(vs);
    float inv = rsqrtf(vs * (1.0f / 2048.0f) + EPS_F);
    #pragma unroll
    for (int i = 0; i < 8; i++) {
        int k = tid + i * 256;
        out[b * 2048 + k] = (av[i] - mu) * inv * gamma[k] + beta[k];
    }
}

// ---------------------------------------------------------------------------
// Launch
// ---------------------------------------------------------------------------
extern "C" void kernel_launch(void* const* d_in, const int* in_sizes, int n_in,
                              void* d_out, int out_size) {
    const int*   tokens = (const int*)  d_in[0];
    const float* emb    = (const float*)d_in[1];
    const float* Wq     = (const float*)d_in[2];
    const float* bq     = (const float*)d_in[3];
    const float* Wk     = (const float*)d_in[4];
    const float* bk     = (const float*)d_in[5];
    const float* Wv     = (const float*)d_in[6];
    const float* bv     = (const float*)d_in[7];
    const float* Wo     = (const float*)d_in[8];
    const float* bo     = (const float*)d_in[9];
    const float* gamma  = (const float*)d_in[10];
    const float* beta   = (const float*)d_in[11];
    float* out = (float*)d_out;

    float *x, *r, *nb, *pmx, *psm;
    __nv_bfloat16 *xb, *qb, *kb, *vb, *cb, *wq, *wk, *wv, *wo;
    cudaGetSymbolAddress((void**)&x,   g_x);
    cudaGetSymbolAddress((void**)&r,   g_r);
    cudaGetSymbolAddress((void**)&nb,  g_nb);
    cudaGetSymbolAddress((void**)&pmx, g_pmx);
    cudaGetSymbolAddress((void**)&psm, g_psm);
    cudaGetSymbolAddress((void**)&xb,  g_xb);
    cudaGetSymbolAddress((void**)&qb,  g_qb);
    cudaGetSymbolAddress((void**)&kb,  g_kb);
    cudaGetSymbolAddress((void**)&vb,  g_vb);
    cudaGetSymbolAddress((void**)&cb,  g_cb);
    cudaGetSymbolAddress((void**)&wq,  g_wq);
    cudaGetSymbolAddress((void**)&wk,  g_wk);
    cudaGetSymbolAddress((void**)&wv,  g_wv);
    cudaGetSymbolAddress((void**)&wo,  g_wo);

    cudaFuncSetAttribute(gemm_bf<true,  false, true>,
                         cudaFuncAttributeMaxDynamicSharedMemorySize, SMEM_BYTES);
    cudaFuncSetAttribute(gemm_bf<true,  true,  false>,
                         cudaFuncAttributeMaxDynamicSharedMemorySize, SMEM_BYTES);
    cudaFuncSetAttribute(flash_kernel,
                         cudaFuncAttributeMaxDynamicSharedMemorySize, FL_SMEM);

    // 1. embed (f32 + bf16), mask, fused weight conversion
    embed_kernel<<<N_B * N_L, 256>>>(tokens, emb, x, xb);
    mask_kernel<<<8, 1024>>>(tokens, nb);
    conv4_kernel<<<8192, 256>>>(Wq, Wk, Wv, Wo, wq, wk, wv, wo);

    // 2. Q/K/V projections -> bf16
    dim3 gProj(8, 64, 1);
    gemm_bf<true, false, true><<<gProj, 256, SMEM_BYTES>>>(
        xb, wq, bq, nullptr, qb, 8192, 1024, 1024);
    gemm_bf<true, false, true><<<gProj, 256, SMEM_BYTES>>>(
        xb, wk, bk, nullptr, kb, 8192, 1024, 1024);
    gemm_bf<true, false, true><<<gProj, 256, SMEM_BYTES>>>(
        xb, wv, bv, nullptr, vb, 8192, 1024, 1024);

    // 3-5. fused attention (QK^T + softmax + PV) -> bf16 ctx
    flash_kernel<<<dim3(8, 64), 256, FL_SMEM>>>(qb, kb, vb, nb, cb);

    // 6. r = x + ctx @ Wo + bo -> f32
    gemm_bf<true, true, false><<<gProj, 256, SMEM_BYTES>>>(
        cb, wo, bo, x, r, 8192, 1024, 1024);

    // 7. pool (sliced) + fused reduce/layernorm
    pool1_kernel<<<dim3(8, 8, 8), 128>>>(r, pmx, psm);
    ln_kernel<<<8, 256>>>(pmx, psm, gamma, beta, out);
}

// round 13
// speedup vs baseline: 6.6440x; 1.0777x over previous
#include <cuda_runtime.h>
#include <cuda_bf16.h>
#include <math.h>

// Shapes (fixed): B=8, L=1024, D=1024, H=8, DH=128, BH=64
#define N_B    8
#define N_L    1024
#define N_D    1024
#define SCALE_F 0.25f
#define EPS_F   1e-5f
#define LOG2E_F 1.4426950408889634f

// ---------------------------------------------------------------------------
// Scratch
// ---------------------------------------------------------------------------
__device__ float g_x[8u * 1024u * 1024u];     // embedded input (f32, residual)
__device__ float g_r[8u * 1024u * 1024u];     // r = x + out (f32)
__device__ float g_nb[8 * 1024];              // -inf mask bias
__device__ float g_pmx[8 * 8 * 1024];         // pool partial max
__device__ float g_psm[8 * 8 * 1024];         // pool partial sum

__device__ __nv_bfloat16 g_xb[8u * 1024u * 1024u];   // x bf16
__device__ __nv_bfloat16 g_qb[8u * 1024u * 1024u];   // Q bf16
__device__ __nv_bfloat16 g_kb[8u * 1024u * 1024u];   // K bf16
__device__ __nv_bfloat16 g_vb[8u * 1024u * 1024u];   // V bf16
__device__ __nv_bfloat16 g_cb[8u * 1024u * 1024u];   // ctx bf16
__device__ __nv_bfloat16 g_wq[1024 * 1024];
__device__ __nv_bfloat16 g_wk[1024 * 1024];
__device__ __nv_bfloat16 g_wv[1024 * 1024];
__device__ __nv_bfloat16 g_wo[1024 * 1024];

// ---------------------------------------------------------------------------
// Helpers
// ---------------------------------------------------------------------------
__device__ __forceinline__ void cpa16(void* dst_smem, const void* src_gmem) {
    unsigned d = (unsigned)__cvta_generic_to_shared(dst_smem);
    asm volatile("cp.async.cg.shared.global [%0], [%1], 16;\n"
                 :: "r"(d), "l"(src_gmem));
}

__device__ __forceinline__ float blockSum(float v) {
    __shared__ float sh[32];
    int lane = threadIdx.x & 31, wid = threadIdx.x >> 5;
    #pragma unroll
    for (int o = 16; o > 0; o >>= 1) v += __shfl_xor_sync(0xffffffffu, v, o);
    if (lane == 0) sh[wid] = v;
    __syncthreads();
    int nw = blockDim.x >> 5;
    float r = (threadIdx.x < (unsigned)nw) ? sh[threadIdx.x] : 0.0f;
    if (wid == 0) {
        #pragma unroll
        for (int o = 16; o > 0; o >>= 1) r += __shfl_xor_sync(0xffffffffu, r, o);
        if (lane == 0) sh[0] = r;
    }
    __syncthreads();
    float out = sh[0];
    __syncthreads();
    return out;
}

// ---------------------------------------------------------------------------
// Embedding (f32 + bf16) + mask + fused 4-weight convert
// ---------------------------------------------------------------------------
__global__ void embed_kernel(const int* __restrict__ tokens,
                             const float* __restrict__ emb,
                             float* __restrict__ x,
                             __nv_bfloat16* __restrict__ xb) {
    int row = blockIdx.x;
    int tok = tokens[row];
    float4 v = ((const float4*)(emb + (long)tok * N_D))[threadIdx.x];
    ((float4*)(x + (long)row * N_D))[threadIdx.x] = v;
    __nv_bfloat162* db = (__nv_bfloat162*)(xb + (long)row * N_D);
    db[2 * threadIdx.x]     = __nv_bfloat162(__float2bfloat16(v.x), __float2bfloat16(v.y));
    db[2 * threadIdx.x + 1] = __nv_bfloat162(__float2bfloat16(v.z), __float2bfloat16(v.w));
}

__global__ void mask_kernel(const int* __restrict__ tokens, float* __restrict__ nb) {
    int i = blockIdx.x * blockDim.x + threadIdx.x;
    nb[i] = (tokens[i] == 0) ? -INFINITY : 0.0f;
}

__global__ void conv4_kernel(const float* __restrict__ s0, const float* __restrict__ s1,
                             const float* __restrict__ s2, const float* __restrict__ s3,
                             __nv_bfloat16* __restrict__ d0, __nv_bfloat16* __restrict__ d1,
                             __nv_bfloat16* __restrict__ d2, __nv_bfloat16* __restrict__ d3) {
    int w = blockIdx.x >> 11;
    const float* src = (w == 0) ? s0 : (w == 1) ? s1 : (w == 2) ? s2 : s3;
    __nv_bfloat16* dst = (w == 0) ? d0 : (w == 1) ? d1 : (w == 2) ? d2 : d3;
    int i = (blockIdx.x & 2047) * blockDim.x + threadIdx.x;
    float2 v = ((const float2*)src)[i];
    ((__nv_bfloat162*)dst)[i] = __nv_bfloat162(__float2bfloat16(v.x), __float2bfloat16(v.y));
}

// ---------------------------------------------------------------------------
// bf16 MMA + ldmatrix
// ---------------------------------------------------------------------------
#define MMA_BF16(d, a, b)                                                     \
    asm volatile(                                                             \
        "mma.sync.aligned.m16n8k16.row.col.f32.bf16.bf16.f32 "                \
        "{%0,%1,%2,%3},{%4,%5,%6,%7},{%8,%9},{%0,%1,%2,%3};"                  \
        : "+f"((d)[0]), "+f"((d)[1]), "+f"((d)[2]), "+f"((d)[3])              \
        : "r"((a)[0]), "r"((a)[1]), "r"((a)[2]), "r"((a)[3]),                 \
          "r"((b)[0]), "r"((b)[1]))

#define LDSM_X4(r0, r1, r2, r3, addr)                                         \
    asm volatile("ldmatrix.sync.aligned.m8n8.x4.shared.b16 {%0,%1,%2,%3}, [%4];" \
                 : "=r"(r0), "=r"(r1), "=r"(r2), "=r"(r3) : "r"(addr))

#define LDSM_X4T(r0, r1, r2, r3, addr)                                        \
    asm volatile("ldmatrix.sync.aligned.m8n8.x4.trans.shared.b16 {%0,%1,%2,%3}, [%4];" \
                 : "=r"(r0), "=r"(r1), "=r"(r2), "=r"(r3) : "r"(addr))

// ---------------------------------------------------------------------------
// GEMM SMEM geometry: 4-stage ring, one barrier per k-tile
// ---------------------------------------------------------------------------
#define A_LDH   40
#define BNN_LDH 136
#define A_H     (128 * A_LDH)
#define B_H     5120
#define STG_H   (A_H + B_H)
#define NSTG    4
#define SMEM_BYTES (NSTG * STG_H * 2)     // 81920 B

// ---------------------------------------------------------------------------
// bf16 NN tensor GEMM. 128x128x32 tile, 256 thr, warp tile 64x32.
//   NMAT=3: z selects (B,bias,C) — fused QKV.  NMAT=1: single (Wo).
//   RES: add f32 residual.  OBF: bf16 output (else f32).
// ---------------------------------------------------------------------------
template <int NMAT, bool RES, bool OBF>
__global__ void __launch_bounds__(256)
gemm_bf(const __nv_bfloat16* __restrict__ A,
        const __nv_bfloat16* B0, const __nv_bfloat16* B1, const __nv_bfloat16* B2,
        const float* bias0, const float* bias1, const float* bias2,
        const float* __restrict__ res,
        void* C0, void* C1, void* C2,
        int M, int N, int K) {
    extern __shared__ __nv_bfloat16 sm[];

    const __nv_bfloat16* B;
    const float* bias;
    void* Cv;
    if (NMAT == 3) {
        int z = blockIdx.z;
        B    = (z == 0) ? B0 : (z == 1) ? B1 : B2;
        bias = (z == 0) ? bias0 : (z == 1) ? bias1 : bias2;
        Cv   = (z == 0) ? C0 : (z == 1) ? C1 : C2;
    } else {
        B = B0; bias = bias0; Cv = C0;
    }

    int tid = threadIdx.x;
    int lane = tid & 31, wid = tid >> 5;
    int warpRow = wid >> 2, warpCol = wid & 3;
    int grp = lane >> 2, qid = lane & 3;

    int row0 = blockIdx.y * 128;
    int col0 = blockIdx.x * 128;
    int KT = K >> 5;

    auto load_tile = [&](int kt, int buf) {
        __nv_bfloat16* Asb = sm + buf * STG_H;
        __nv_bfloat16* Bsb = Asb + A_H;
        int k0 = kt << 5;
        #pragma unroll
        for (int p = 0; p < 2; p++) {
            int idx = p * 256 + tid;
            int r = idx >> 2, cc = (idx & 3) << 3;
            cpa16(Asb + r * A_LDH + cc, A + (long)(row0 + r) * K + k0 + cc);
        }
        #pragma unroll
        for (int p = 0; p < 2; p++) {
            int idx = p * 256 + tid;
            int r = idx >> 4, cc = (idx & 15) << 3;
            cpa16(Bsb + r * BNN_LDH + cc, B + (long)(k0 + r) * N + col0 + cc);
        }
    };

    float acc[4][4][4];
    #pragma unroll
    for (int i = 0; i < 4; i++)
        #pragma unroll
        for (int j = 0; j < 4; j++)
            #pragma unroll
            for (int t = 0; t < 4; t++) acc[i][j][t] = 0.0f;

    // prologue: stages 0..2
    load_tile(0, 0);
    asm volatile("cp.async.commit_group;\n" ::);
    load_tile(1, 1);
    asm volatile("cp.async.commit_group;\n" ::);
    load_tile(2, 2);
    asm volatile("cp.async.commit_group;\n" ::);

    for (int kt = 0; kt < KT; kt++) {
        asm volatile("cp.async.wait_group 2;\n" ::);
        __syncthreads();          // all warps done with stage (kt-1)%4; stage kt%4 ready

        // prefetch stage kt+3 into ring slot (kt+3)%4 == (kt-1)%4
        if (kt + 3 < KT) load_tile(kt + 3, (kt + 3) & 3);
        asm volatile("cp.async.commit_group;\n" ::);

        __nv_bfloat16* Asb = sm + (kt & 3) * STG_H;
        __nv_bfloat16* Bsb = Asb + A_H;
        unsigned AsU = (unsigned)__cvta_generic_to_shared(Asb);
        unsigned BsU = (unsigned)__cvta_generic_to_shared(Bsb);

        #pragma unroll
        for (int ks = 0; ks < 2; ks++) {
            int k0h = ks * 16;
            unsigned a[4][4];
            #pragma unroll
            for (int i = 0; i < 4; i++) {
                int r = warpRow * 64 + i * 16 + (lane & 15);
                unsigned ad = AsU + (r * A_LDH + k0h + ((lane >> 4) << 3)) * 2;
                LDSM_X4(a[i][0], a[i][1], a[i][2], a[i][3], ad);
            }
            unsigned b[4][2];
            #pragma unroll
            for (int j2 = 0; j2 < 2; j2++) {
                int n0 = warpCol * 32 + j2 * 16;
                int r = k0h + (((lane >> 3) & 1) << 3) + (lane & 7);
                int c = n0 + ((lane >> 4) << 3);
                unsigned ad = BsU + (r * BNN_LDH + c) * 2;
                LDSM_X4T(b[2 * j2][0], b[2 * j2][1], b[2 * j2 + 1][0], b[2 * j2 + 1][1], ad);
            }
            #pragma unroll
            for (int i = 0; i < 4; i++)
                #pragma unroll
                for (int j = 0; j < 4; j++)
                    MMA_BF16(acc[i][j], a[i], b[j]);
        }
    }

    #pragma unroll
    for (int i = 0; i < 4; i++) {
        int r = row0 + warpRow * 64 + i * 16 + grp;
        #pragma unroll
        for (int j = 0; j < 4; j++) {
            int c = col0 + warpCol * 32 + j * 8 + 2 * qid;
            float2 v0 = make_float2(acc[i][j][0], acc[i][j][1]);
            float2 v1 = make_float2(acc[i][j][2], acc[i][j][3]);
            float2 bb = *(const float2*)(bias + c);
            v0.x += bb.x; v0.y += bb.y;
            v1.x += bb.x; v1.y += bb.y;
            if (RES) {
                float2 r0v = *(const float2*)(res + (long)r * N + c);
                float2 r1v = *(const float2*)(res + (long)(r + 8) * N + c);
                v0.x += r0v.x; v0.y += r0v.y;
                v1.x += r1v.x; v1.y += r1v.y;
            }
            if (OBF) {
                __nv_bfloat16* C = (__nv_bfloat16*)Cv;
                *(__nv_bfloat162*)(C + (long)r * N + c) =
                    __nv_bfloat162(__float2bfloat16(v0.x), __float2bfloat16(v0.y));
                *(__nv_bfloat162*)(C + (long)(r + 8) * N + c) =
                    __nv_bfloat162(__float2bfloat16(v1.x), __float2bfloat16(v1.y));
            } else {
                float* C = (float*)Cv;
                *(float2*)(C + (long)r * N + c)       = v0;
                *(float2*)(C + (long)(r + 8) * N + c) = v1;
            }
        }
    }
}

// ---------------------------------------------------------------------------
// Fused flash attention, 64-row KV tiles, 2 CTAs/SM (unchanged from R11)
// ---------------------------------------------------------------------------
#define FL_LDH     136
#define FL_Q_H     (128 * FL_LDH)
#define FL_KV_H    (64 * FL_LDH)
#define FL_SMEM    ((FL_Q_H + 4 * FL_KV_H) * 2)

__global__ void __launch_bounds__(256, 2)
flash_kernel(const __nv_bfloat16* __restrict__ Q,
             const __nv_bfloat16* __restrict__ K,
             const __nv_bfloat16* __restrict__ V,
             const float* __restrict__ nb,
             __nv_bfloat16* __restrict__ Octx) {
    extern __shared__ __nv_bfloat16 fsm[];
    __nv_bfloat16* Qs = fsm;
    __nv_bfloat16* Ks = fsm + FL_Q_H;
    __nv_bfloat16* Vs = fsm + FL_Q_H + 2 * FL_KV_H;

    int tid = threadIdx.x;
    int lane = tid & 31, wid = tid >> 5;
    int grp = lane >> 2, qid = lane & 3;
    int m0 = wid * 16;

    int bh = blockIdx.y;
    int q0 = blockIdx.x * 128;
    const __nv_bfloat16* Qg = Q + (long)bh * 131072 + (long)q0 * 128;
    const __nv_bfloat16* Kg = K + (long)bh * 131072;
    const __nv_bfloat16* Vg = V + (long)bh * 131072;
    const float* nbr = nb + ((bh & 7) << 10);
    __nv_bfloat16* Cg = Octx + (long)bh * 131072 + (long)q0 * 128;

    auto loadKV = [&](int kt, int stg) {
        const __nv_bfloat16* Kt = Kg + (long)kt * 8192;
        const __nv_bfloat16* Vt = Vg + (long)kt * 8192;
        __nv_bfloat16* Kd = Ks + stg * FL_KV_H;
        __nv_bfloat16* Vd = Vs + stg * FL_KV_H;
        #pragma unroll
        for (int p = 0; p < 4; p++) {
            int idx = p * 256 + tid;
            int r = idx >> 4, cc = (idx & 15) << 3;
            cpa16(Kd + r * FL_LDH + cc, Kt + r * 128 + cc);
        }
        #pragma unroll
        for (int p = 0; p < 4; p++) {
            int idx = p * 256 + tid;
            int r = idx >> 4, cc = (idx & 15) << 3;
            cpa16(Vd + r * FL_LDH + cc, Vt + r * 128 + cc);
        }
    };

    #pragma unroll
    for (int p = 0; p < 8; p++) {
        int idx = p * 256 + tid;
        int r = idx >> 4, cc = (idx & 15) << 3;
        cpa16(Qs + r * FL_LDH + cc, Qg + r * 128 + cc);
    }
    loadKV(0, 0);
    asm volatile("cp.async.commit_group;\n" ::);

    float o[16][4];
    #pragma unroll
    for (int j = 0; j < 16; j++)
        #pragma unroll
        for (int t = 0; t < 4; t++) o[j][t] = 0.0f;
    float mrow0 = -1e30f, mrow1 = -1e30f;
    float lrow0 = 0.0f,  lrow1 = 0.0f;

    unsigned QsU = (unsigned)__cvta_generic_to_shared(Qs);

    #pragma unroll 1
    for (int kt = 0; kt < 16; kt++) {
        int stg = kt & 1;
        if (kt < 15) loadKV(kt + 1, stg ^ 1);
        asm volatile("cp.async.commit_group;\n" ::);
        asm volatile("cp.async.wait_group 1;\n" ::);
        __syncthreads();

        unsigned KsU = (unsigned)__cvta_generic_to_shared(Ks + stg * FL_KV_H);
        unsigned VsU = (unsigned)__cvta_generic_to_shared(Vs + stg * FL_KV_H);

        float s[8][4];
        #pragma unroll
        for (int j = 0; j < 8; j++)
            #pragma unroll
            for (int t = 0; t < 4; t++) s[j][t] = 0.0f;

        #pragma unroll
        for (int kf = 0; kf < 8; kf++) {
            unsigned aq[4];
            {
                int r = m0 + (lane & 15);
                int c = kf * 16 + ((lane >> 4) << 3);
                LDSM_X4(aq[0], aq[1], aq[2], aq[3], QsU + (r * FL_LDH + c) * 2);
            }
            #pragma unroll
            for (int j2 = 0; j2 < 4; j2++) {
                unsigned bq[4];
                int rn = j2 * 16 + ((lane >> 4) << 3) + (lane & 7);
                int ck = kf * 16 + (((lane >> 3) & 1) << 3);
                LDSM_X4(bq[0], bq[1], bq[2], bq[3], KsU + (rn * FL_LDH + ck) * 2);
                MMA_BF16(s[2 * j2],     aq, bq);
                MMA_BF16(s[2 * j2 + 1], aq, (bq + 2));
            }
        }

        int kb = kt << 6;
        float mx0 = mrow0, mx1 = mrow1;
        #pragma unroll
        for (int j = 0; j < 8; j++) {
            float2 msk = *(const float2*)(nbr + kb + j * 8 + 2 * qid);
            s[j][0] = fmaf(s[j][0], SCALE_F, msk.x);
            s[j][1] = fmaf(s[j][1], SCALE_F, msk.y);
            s[j][2] = fmaf(s[j][2], SCALE_F, msk.x);
            s[j][3] = fmaf(s[j][3], SCALE_F, msk.y);
            mx0 = fmaxf(mx0, fmaxf(s[j][0], s[j][1]));
            mx1 = fmaxf(mx1, fmaxf(s[j][2], s[j][3]));
        }
        mx0 = fmaxf(mx0, __shfl_xor_sync(0xffffffffu, mx0, 1));
        mx0 = fmaxf(mx0, __shfl_xor_sync(0xffffffffu, mx0, 2));
        mx1 = fmaxf(mx1, __shfl_xor_sync(0xffffffffu, mx1, 1));
        mx1 = fmaxf(mx1, __shfl_xor_sync(0xffffffffu, mx1, 2));

        float al0 = exp2f((mrow0 - mx0) * LOG2E_F);
        float al1 = exp2f((mrow1 - mx1) * LOG2E_F);
        mrow0 = mx0; mrow1 = mx1;

        float r0 = 0.0f, r1 = 0.0f;
        #pragma unroll
        for (int j = 0; j < 8; j++) {
            s[j][0] = exp2f((s[j][0] - mx0) * LOG2E_F);
            s[j][1] = exp2f((s[j][1] - mx0) * LOG2E_F);
            s[j][2] = exp2f((s[j][2] - mx1) * LOG2E_F);
            s[j][3] = exp2f((s[j][3] - mx1) * LOG2E_F);
            r0 += s[j][0] + s[j][1];
            r1 += s[j][2] + s[j][3];
        }
        #pragma unroll
        for (int j = 0; j < 16; j++) {
            o[j][0] *= al0; o[j][1] *= al0;
            o[j][2] *= al1; o[j][3] *= al1;
        }
        lrow0 = lrow0 * al0 + r0;
        lrow1 = lrow1 * al1 + r1;

        #pragma unroll
        for (int t = 0; t < 4; t++) {
            unsigned ap[4];
            __nv_bfloat162 p0 = __floats2bfloat162_rn(s[2 * t][0],     s[2 * t][1]);
            __nv_bfloat162 p1 = __floats2bfloat162_rn(s[2 * t][2],     s[2 * t][3]);
            __nv_bfloat162 p2 = __floats2bfloat162_rn(s[2 * t + 1][0], s[2 * t + 1][1]);
            __nv_bfloat162 p3 = __floats2bfloat162_rn(s[2 * t + 1][2], s[2 * t + 1][3]);
            ap[0] = *(unsigned*)&p0;
            ap[1] = *(unsigned*)&p1;
            ap[2] = *(unsigned*)&p2;
            ap[3] = *(unsigned*)&p3;
            #pragma unroll
            for (int j2 = 0; j2 < 8; j2++) {
                unsigned bv[4];
                int rk = t * 16 + (((lane >> 3) & 1) << 3) + (lane & 7);
                int cn = j2 * 16 + ((lane >> 4) << 3);
                LDSM_X4T(bv[0], bv[1], bv[2], bv[3], VsU + (rk * FL_LDH + cn) * 2);
                MMA_BF16(o[2 * j2],     ap, bv);
                MMA_BF16(o[2 * j2 + 1], ap, (bv + 2));
            }
        }
        __syncthreads();
    }

    lrow0 += __shfl_xor_sync(0xffffffffu, lrow0, 1);
    lrow0 += __shfl_xor_sync(0xffffffffu, lrow0, 2);
    lrow1 += __shfl_xor_sync(0xffffffffu, lrow1, 1);
    lrow1 += __shfl_xor_sync(0xffffffffu, lrow1, 2);
    float inv0 = 1.0f / lrow0;
    float inv1 = 1.0f / lrow1;

    int r0i = m0 + grp, r1i = m0 + grp + 8;
    #pragma unroll
    for (int j = 0; j < 16; j++) {
        int c = j * 8 + 2 * qid;
        *(__nv_bfloat162*)(Cg + (long)r0i * 128 + c) =
            __floats2bfloat162_rn(o[j][0] * inv0, o[j][1] * inv0);
        *(__nv_bfloat162*)(Cg + (long)r1i * 128 + c) =
            __floats2bfloat162_rn(o[j][2] * inv1, o[j][3] * inv1);
    }
}

// ---------------------------------------------------------------------------
// Pooling (sliced) + fused reduce/LayerNorm
// ---------------------------------------------------------------------------
__global__ void pool1_kernel(const float* __restrict__ r,
                             float* __restrict__ pmx, float* __restrict__ psm) {
    int b = blockIdx.x, dc = blockIdx.y, sl = blockIdx.z;
    int d = dc * 128 + threadIdx.x;
    const float* base = r + ((long)b << 20) + ((long)sl << 17) + d;
    float mx = -INFINITY, sm = 0.0f;
    #pragma unroll 4
    for (int l = 0; l < 128; l++) {
        float v = base[(long)l << 10];
        mx = fmaxf(mx, v);
        sm += v;
    }
    pmx[(((b << 3) + sl) << 10) + d] = mx;
    psm[(((b << 3) + sl) << 10) + d] = sm;
}

__global__ void __launch_bounds__(256)
ln_kernel(const float* __restrict__ pmx, const float* __restrict__ psm,
          const float* __restrict__ gamma, const float* __restrict__ beta,
          float* __restrict__ out) {
    int b = blockIdx.x, tid = threadIdx.x;
    float av[8];
    #pragma unroll
    for (int i = 0; i < 8; i++) {
        int k = tid + i * 256;
        if (k < 1024) {
            float mx = -INFINITY;
            #pragma unroll
            for (int sl = 0; sl < 8; sl++)
                mx = fmaxf(mx, pmx[(((b << 3) + sl) << 10) + k]);
            av[i] = mx;
        } else {
            int d = k - 1024;
            float sm = 0.0f;
            #pragma unroll
            for (int sl = 0; sl < 8; sl++)
                sm += psm[(((b << 3) + sl) << 10) + d];
            av[i] = sm * (1.0f / 1024.0f);
        }
    }
    float s = 0.0f;
    #pragma unroll
    for (int i = 0; i < 8; i++) s += av[i];
    s = blockSum(s);
    float mu = s * (1.0f / 2048.0f);
    float vs = 0.0f;
    #pragma unroll
    for (int i = 0; i < 8; i++) {
        float d = av[i] - mu;
        vs += d * d;
    }
    vs = blockSum(vs);
    float inv = rsqrtf(vs * (1.0f / 2048.0f) + EPS_F);
    #pragma unroll
    for (int i = 0; i < 8; i++) {
        int k = tid + i * 256;
        out[b * 2048 + k] = (av[i] - mu) * inv * gamma[k] + beta[k];
    }
}

// ---------------------------------------------------------------------------
// Launch
// ---------------------------------------------------------------------------
extern "C" void kernel_launch(void* const* d_in, const int* in_sizes, int n_in,
                              void* d_out, int out_size) {
    const int*   tokens = (const int*)  d_in[0];
    const float* emb    = (const float*)d_in[1];
    const float* Wq     = (const float*)d_in[2];
    const float* bq     = (const float*)d_in[3];
    const float* Wk     = (const float*)d_in[4];
    const float* bk     = (const float*)d_in[5];
    const float* Wv     = (const float*)d_in[6];
    const float* bv     = (const float*)d_in[7];
    const float* Wo     = (const float*)d_in[8];
    const float* bo     = (const float*)d_in[9];
    const float* gamma  = (const float*)d_in[10];
    const float* beta   = (const float*)d_in[11];
    float* out = (float*)d_out;

    float *x, *r, *nb, *pmx, *psm;
    __nv_bfloat16 *xb, *qb, *kb, *vb, *cb, *wq, *wk, *wv, *wo;
    cudaGetSymbolAddress((void**)&x,   g_x);
    cudaGetSymbolAddress((void**)&r,   g_r);
    cudaGetSymbolAddress((void**)&nb,  g_nb);
    cudaGetSymbolAddress((void**)&pmx, g_pmx);
    cudaGetSymbolAddress((void**)&psm, g_psm);
    cudaGetSymbolAddress((void**)&xb,  g_xb);
    cudaGetSymbolAddress((void**)&qb,  g_qb);
    cudaGetSymbolAddress((void**)&kb,  g_kb);
    cudaGetSymbolAddress((void**)&vb,  g_vb);
    cudaGetSymbolAddress((void**)&cb,  g_cb);
    cudaGetSymbolAddress((void**)&wq,  g_wq);
    cudaGetSymbolAddress((void**)&wk,  g_wk);
    cudaGetSymbolAddress((void**)&wv,  g_wv);
    cudaGetSymbolAddress((void**)&wo,  g_wo);

    cudaFuncSetAttribute(gemm_bf<3, false, true>,
                         cudaFuncAttributeMaxDynamicSharedMemorySize, SMEM_BYTES);
    cudaFuncSetAttribute(gemm_bf<1, true, false>,
                         cudaFuncAttributeMaxDynamicSharedMemorySize, SMEM_BYTES);
    cudaFuncSetAttribute(flash_kernel,
                         cudaFuncAttributeMaxDynamicSharedMemorySize, FL_SMEM);

    // 1. embed (f32 + bf16), mask, fused weight conversion
    embed_kernel<<<N_B * N_L, 256>>>(tokens, emb, x, xb);
    mask_kernel<<<8, 1024>>>(tokens, nb);
    conv4_kernel<<<8192, 256>>>(Wq, Wk, Wv, Wo, wq, wk, wv, wo);

    // 2. fused Q/K/V projections -> bf16 (one launch, z selects weight)
    dim3 gQKV(8, 64, 3);
    gemm_bf<3, false, true><<<gQKV, 256, SMEM_BYTES>>>(
        xb, wq, wk, wv, bq, bk, bv, nullptr,
        qb, kb, vb, 8192, 1024, 1024);

    // 3-5. fused flash attention -> bf16 ctx
    flash_kernel<<<dim3(8, 64), 256, FL_SMEM>>>(qb, kb, vb, nb, cb);

    // 6. r = x + ctx @ Wo + bo -> f32
    dim3 gWo(8, 64, 1);
    gemm_bf<1, true, false><<<gWo, 256, SMEM_BYTES>>>(
        cb, wo, nullptr, nullptr, bo, nullptr, nullptr, x,
        r, nullptr, nullptr, 8192, 1024, 1024);

    // 7. pool + layernorm
    pool1_kernel<<<dim3(8, 8, 8), 128>>>(r, pmx, psm);
    ln_kernel<<<8, 256>>>(pmx, psm, gamma, beta, out);
}